// round 2
// baseline (speedup 1.0000x reference)
#include <cuda_runtime.h>
#include <math.h>

#define B_    256
#define N_    200
#define FIN   768
#define HID   32
#define NH    8
#define FC    256                 // NH*HID
#define ROWS  (B_*N_)             // 51200
#define ALPHA 0.3f
#define NEGINF (-9e15f)

// ---------------- scratch (device globals; no allocations allowed) ----------
__device__ float     g_H1[(size_t)ROWS*FC];     // first layer h, [row][head*32+f]
__device__ float     g_X2[(size_t)ROWS*FC];     // post ELU+BN concat features
__device__ float     g_s1[(size_t)NH*ROWS];     // [h][row]
__device__ float     g_s2[(size_t)NH*ROWS];
__device__ unsigned  g_mask[(size_t)ROWS*8];    // 7 words of adj bits per row (pad 8)
__device__ float     g_hs[(size_t)ROWS*2];
__device__ float     g_hp[(size_t)ROWS*2];
__device__ float     g_hq[(size_t)ROWS*HID];
__device__ float     g_s1s[ROWS], g_s2s[ROWS];
__device__ float     g_s1p[ROWS], g_s2p[ROWS];
__device__ float     g_s1q[ROWS], g_s2q[ROWS];

__device__ __forceinline__ float eluf(float v)  { return v > 0.f ? v : expm1f(v); }
__device__ __forceinline__ float lrelu(float v) { return v > 0.f ? v : ALPHA * v; }

// ---------------- 1) adjacency -> bitmask via ballot -------------------------
__global__ __launch_bounds__(256) void mask_kernel(const int* __restrict__ adj)
{
    int gw   = (blockIdx.x * blockDim.x + threadIdx.x) >> 5;
    int lane = threadIdx.x & 31;
    if (gw >= ROWS) return;
    const int* row = adj + (size_t)gw * N_;
    unsigned*  dst = g_mask + (size_t)gw * 8;
    #pragma unroll
    for (int w = 0; w < 7; ++w) {
        int j = w * 32 + lane;
        int v = (j < N_) ? (row[j] > 0) : 0;
        unsigned bits = __ballot_sync(0xffffffffu, v);
        if (lane == 0) dst[w] = bits;
    }
}

// ---------------- 2) H1 = feat @ Wcat  (M=51200, N=256, K=768) ---------------
// 128x64 block tile, 8x4 per thread, K-tile 16, 256 threads.
__global__ __launch_bounds__(256) void gemm1_kernel(const float* __restrict__ A,
                                                    const float* __restrict__ Wh)
{
    __shared__ __align__(16) float As[16][128];
    __shared__ __align__(16) float Bs[16][64];

    int tid = threadIdx.x;
    int blockRow = blockIdx.y * 128;
    int blockCol = blockIdx.x * 64;
    int tx = tid & 15, ty = tid >> 4;

    int aRow = tid >> 2;            // 0..63 (second row = +64)
    int aK   = (tid & 3) << 2;      // 0,4,8,12
    int bC   = (tid << 2) & 63;     // col in tile, multiple of 4
    int bK   = (tid << 2) >> 6;     // 0..15
    int col  = blockCol + bC;
    const float* Bbase = Wh + (size_t)(col >> 5) * FIN * HID + (col & 31);

    float acc[8][4];
    #pragma unroll
    for (int r = 0; r < 8; ++r)
        #pragma unroll
        for (int c = 0; c < 4; ++c) acc[r][c] = 0.f;

    for (int k0 = 0; k0 < FIN; k0 += 16) {
        float4 a0 = *(const float4*)(A + (size_t)(blockRow + aRow)      * FIN + k0 + aK);
        float4 a1 = *(const float4*)(A + (size_t)(blockRow + aRow + 64) * FIN + k0 + aK);
        As[aK+0][aRow] = a0.x; As[aK+1][aRow] = a0.y; As[aK+2][aRow] = a0.z; As[aK+3][aRow] = a0.w;
        As[aK+0][aRow+64] = a1.x; As[aK+1][aRow+64] = a1.y; As[aK+2][aRow+64] = a1.z; As[aK+3][aRow+64] = a1.w;
        float4 bv = *(const float4*)(Bbase + (size_t)(k0 + bK) * HID);
        *(float4*)&Bs[bK][bC] = bv;
        __syncthreads();

        #pragma unroll
        for (int k = 0; k < 16; ++k) {
            float4 t0 = *(float4*)&As[k][ty*8];
            float4 t1 = *(float4*)&As[k][ty*8+4];
            float4 br = *(float4*)&Bs[k][tx*4];
            float ar[8] = {t0.x,t0.y,t0.z,t0.w,t1.x,t1.y,t1.z,t1.w};
            #pragma unroll
            for (int r = 0; r < 8; ++r) {
                acc[r][0] += ar[r]*br.x; acc[r][1] += ar[r]*br.y;
                acc[r][2] += ar[r]*br.z; acc[r][3] += ar[r]*br.w;
            }
        }
        __syncthreads();
    }

    int cCol = blockCol + tx*4;
    #pragma unroll
    for (int r = 0; r < 8; ++r) {
        size_t row = (size_t)(blockRow + ty*8 + r);
        float4 st = make_float4(acc[r][0], acc[r][1], acc[r][2], acc[r][3]);
        *(float4*)(g_H1 + row * FC + cCol) = st;
    }
}

// ---------------- 3) per-head attention scores s1,s2 -------------------------
__global__ __launch_bounds__(256) void s_kernel(const float* __restrict__ ah)
{
    int gid = blockIdx.x * blockDim.x + threadIdx.x;
    if (gid >= ROWS * NH) return;
    int row = gid >> 3, h = gid & 7;
    const float* a1 = ah + h * 64;
    const float* a2 = a1 + 32;
    const float4* x = (const float4*)(g_H1 + (size_t)row * FC + h * HID);
    float s1 = 0.f, s2 = 0.f;
    #pragma unroll
    for (int t = 0; t < 8; ++t) {
        float4 v = x[t];
        s1 += v.x*a1[4*t] + v.y*a1[4*t+1] + v.z*a1[4*t+2] + v.w*a1[4*t+3];
        s2 += v.x*a2[4*t] + v.y*a2[4*t+1] + v.z*a2[4*t+2] + v.w*a2[4*t+3];
    }
    g_s1[(size_t)h*ROWS + row] = s1;
    g_s2[(size_t)h*ROWS + row] = s2;
}

// ---------------- 4) layer-1 attention + ELU + BN -> X2 ----------------------
__global__ __launch_bounds__(256) void attn1_kernel(const float* __restrict__ bn_g,
                                                    const float* __restrict__ bn_b,
                                                    const float* __restrict__ bn_m,
                                                    const float* __restrict__ bn_v)
{
    int b = blockIdx.x >> 3, h = blockIdx.x & 7;
    __shared__ __align__(16) float sh_h[N_*HID];
    __shared__ float sh_s1[N_], sh_s2[N_];
    __shared__ unsigned shm[N_*7];
    int tid = threadIdx.x;
    size_t base = (size_t)b * N_;

    for (int idx = tid; idx < N_*8; idx += 256) {
        int n = idx >> 3, q = idx & 7;
        ((float4*)sh_h)[idx] = *(const float4*)(g_H1 + (base + n) * FC + h*HID + q*4);
    }
    for (int idx = tid; idx < N_; idx += 256) {
        sh_s1[idx] = g_s1[(size_t)h*ROWS + base + idx];
        sh_s2[idx] = g_s2[(size_t)h*ROWS + base + idx];
    }
    for (int idx = tid; idx < N_*7; idx += 256)
        shm[idx] = g_mask[(base + idx/7)*8 + idx%7];
    __syncthreads();

    int i = tid;
    if (i < N_) {
        const unsigned* mrow = &shm[i*7];
        float s1i = sh_s1[i];
        float m = -3.4e38f;
        for (int j = 0; j < N_; ++j) {
            float t = lrelu(s1i + sh_s2[j]);
            float e = ((mrow[j>>5] >> (j&31)) & 1) ? t : NEGINF;
            m = fmaxf(m, e);
        }
        float acc[HID];
        #pragma unroll
        for (int f = 0; f < HID; ++f) acc[f] = 0.f;
        float l = 0.f;
        for (int j = 0; j < N_; ++j) {
            float t = lrelu(s1i + sh_s2[j]);
            float e = ((mrow[j>>5] >> (j&31)) & 1) ? t : NEGINF;
            float p = __expf(e - m);
            l += p;
            const float4* hv = (const float4*)(sh_h + j*HID);
            #pragma unroll
            for (int q = 0; q < 8; ++q) {
                float4 v = hv[q];
                acc[4*q]   += p*v.x; acc[4*q+1] += p*v.y;
                acc[4*q+2] += p*v.z; acc[4*q+3] += p*v.w;
            }
        }
        float invl = 1.f / l;
        float inv  = bn_g[i] * rsqrtf(bn_v[i] + 1e-5f);
        float bb   = bn_b[i] - bn_m[i] * inv;
        float* dst = g_X2 + (base + i) * FC + h*HID;
        #pragma unroll
        for (int f = 0; f < HID; f += 4) {
            float4 o;
            o.x = eluf(acc[f+0]*invl) * inv + bb;
            o.y = eluf(acc[f+1]*invl) * inv + bb;
            o.z = eluf(acc[f+2]*invl) * inv + bb;
            o.w = eluf(acc[f+3]*invl) * inv + bb;
            *(float4*)(dst + f) = o;
        }
    }
}

// ---------------- 5) second-stage linears + attention scalars ----------------
// cols: 0,1 sent | 2,3 para | 4..35 qt.  W staged [c][k] -> conflict-free.
__global__ __launch_bounds__(256) void lin2_kernel(const float* __restrict__ Wsent,
                                                   const float* __restrict__ asent,
                                                   const float* __restrict__ Wpara,
                                                   const float* __restrict__ apara,
                                                   const float* __restrict__ Wqt,
                                                   const float* __restrict__ aqt)
{
    __shared__ float Wall[36*256];
    int tid = threadIdx.x;
    for (int idx = tid; idx < 512; idx += 256) {
        int k = idx >> 1, c = idx & 1;
        Wall[c*256 + k]     = Wsent[idx];
        Wall[(2+c)*256 + k] = Wpara[idx];
    }
    for (int idx = tid; idx < 8192; idx += 256) {
        int k = idx >> 5, f = idx & 31;
        Wall[(4+f)*256 + k] = Wqt[idx];
    }
    __syncthreads();

    int warp = tid >> 5, lane = tid & 31;
    int nwarps = (gridDim.x * 256) >> 5;
    for (int row = blockIdx.x*8 + warp; row < ROWS; row += nwarps) {
        const float* x = g_X2 + (size_t)row * FC;
        float xr[8];
        #pragma unroll
        for (int t = 0; t < 8; ++t) xr[t] = x[lane + 32*t];

        float s1sv=0,s2sv=0,s1pv=0,s2pv=0,s1qv=0,s2qv=0;
        #pragma unroll 4
        for (int c = 0; c < 36; ++c) {
            const float* wc = Wall + c*256;
            float s = 0.f;
            #pragma unroll
            for (int t = 0; t < 8; ++t) s += xr[t] * wc[lane + 32*t];
            #pragma unroll
            for (int o = 16; o; o >>= 1) s += __shfl_xor_sync(0xffffffffu, s, o);
            if (lane == 0) {
                if (c < 2)       { g_hs[row*2+c]   = s; s1sv += s*asent[c];   s2sv += s*asent[2+c]; }
                else if (c < 4)  { int cc=c-2; g_hp[row*2+cc] = s; s1pv += s*apara[cc]; s2pv += s*apara[2+cc]; }
                else             { int f=c-4;  g_hq[(size_t)row*HID+f] = s; s1qv += s*aqt[f]; s2qv += s*aqt[32+f]; }
            }
        }
        if (lane == 0) {
            g_s1s[row]=s1sv; g_s2s[row]=s2sv;
            g_s1p[row]=s1pv; g_s2p[row]=s2pv;
            g_s1q[row]=s1qv; g_s2q[row]=s2qv;
        }
    }
}

// ---------------- 6) final attentions + heads (sent/para full, qt row 0) -----
__global__ __launch_bounds__(256) void attn2_kernel(const float* __restrict__ W2,
                                                    float* __restrict__ out)
{
    int b = blockIdx.x, tid = threadIdx.x;
    __shared__ float s1s[N_], s2s[N_], s1p[N_], s2p[N_];
    __shared__ float hs[N_*2], hp[N_*2];
    __shared__ unsigned shm[N_*7];
    __shared__ float eq[256];
    __shared__ float h0[HID];
    __shared__ float red[2];
    size_t base = (size_t)b * N_;

    for (int idx = tid; idx < N_; idx += 256) {
        s1s[idx]=g_s1s[base+idx]; s2s[idx]=g_s2s[base+idx];
        s1p[idx]=g_s1p[base+idx]; s2p[idx]=g_s2p[base+idx];
    }
    for (int idx = tid; idx < N_*2; idx += 256) {
        hs[idx]=g_hs[base*2+idx]; hp[idx]=g_hp[base*2+idx];
    }
    for (int idx = tid; idx < N_*7; idx += 256)
        shm[idx] = g_mask[(base + idx/7)*8 + idx%7];
    __syncthreads();

    int i = tid;
    if (i < N_) {
        const unsigned* mrow = &shm[i*7];
        float a1 = s1s[i], p1 = s1p[i];
        float ms = -3.4e38f, mp = -3.4e38f;
        for (int j = 0; j < N_; ++j) {
            int bit = (mrow[j>>5] >> (j&31)) & 1;
            float ts = lrelu(a1 + s2s[j]); ts = bit ? ts : NEGINF;
            float tp = lrelu(p1 + s2p[j]); tp = bit ? tp : NEGINF;
            ms = fmaxf(ms, ts); mp = fmaxf(mp, tp);
        }
        float ls=0.f, lp=0.f, as0=0.f, as1=0.f, ap0=0.f, ap1=0.f;
        for (int j = 0; j < N_; ++j) {
            int bit = (mrow[j>>5] >> (j&31)) & 1;
            float ts = lrelu(a1 + s2s[j]); ts = bit ? ts : NEGINF;
            float ps = __expf(ts - ms); ls += ps;
            as0 += ps*hs[j*2]; as1 += ps*hs[j*2+1];
            float tp = lrelu(p1 + s2p[j]); tp = bit ? tp : NEGINF;
            float pp = __expf(tp - mp); lp += pp;
            ap0 += pp*hp[j*2]; ap1 += pp*hp[j*2+1];
        }
        float o0 = as0/ls, o1 = as1/ls;
        out[(base+i)*2+0] = 1.f/(1.f+__expf(-o0));
        out[(base+i)*2+1] = 1.f/(1.f+__expf(-o1));
        float q0 = ap0/lp, q1 = ap1/lp;
        out[102400 + (base+i)*2+0] = eluf(q0);
        out[102400 + (base+i)*2+1] = eluf(q1);
    }

    // qtype: attention row 0 only
    float s1q0 = g_s1q[base];
    if (tid < N_) {
        int bit = (shm[tid>>5] >> (tid&31)) & 1;   // row 0 mask words
        float t = lrelu(s1q0 + g_s2q[base + tid]);
        eq[tid] = bit ? t : NEGINF;
    } else eq[tid] = -3.4e38f;
    __syncthreads();
    if (tid < 32) {
        float v = -3.4e38f;
        for (int j = tid; j < N_; j += 32) v = fmaxf(v, eq[j]);
        #pragma unroll
        for (int o = 16; o; o >>= 1) v = fmaxf(v, __shfl_xor_sync(0xffffffffu, v, o));
        if (tid == 0) red[0] = v;
    }
    __syncthreads();
    float mq = red[0];
    if (tid < N_) eq[tid] = __expf(eq[tid] - mq);
    __syncthreads();
    if (tid < 32) {
        float v = 0.f;
        for (int j = tid; j < N_; j += 32) v += eq[j];
        #pragma unroll
        for (int o = 16; o; o >>= 1) v += __shfl_xor_sync(0xffffffffu, v, o);
        if (tid == 0) red[1] = v;
    }
    __syncthreads();
    float lq = red[1];
    if (tid < 32) {
        float acc = 0.f;
        for (int j = 0; j < N_; ++j) acc += eq[j] * g_hq[(base + j)*HID + tid];
        h0[tid] = acc / lq;
    }
    __syncthreads();
    if (tid < 2) {
        float s = 0.f;
        #pragma unroll
        for (int f = 0; f < HID; ++f) s += h0[f] * W2[f*2 + tid];
        out[204800 + b*2 + tid] = eluf(s);
    }
}

// ---------------------------------------------------------------------------
extern "C" void kernel_launch(void* const* d_in, const int* in_sizes, int n_in,
                              void* d_out, int out_size)
{
    const float* feat  = (const float*)d_in[0];
    const int*   adj   = (const int*)  d_in[1];
    const float* Wh    = (const float*)d_in[2];
    const float* ah    = (const float*)d_in[3];
    const float* Wsent = (const float*)d_in[4];
    const float* asent = (const float*)d_in[5];
    const float* Wpara = (const float*)d_in[6];
    const float* apara = (const float*)d_in[7];
    const float* Wqt   = (const float*)d_in[8];
    const float* aqt   = (const float*)d_in[9];
    const float* W2    = (const float*)d_in[10];
    const float* bn_g  = (const float*)d_in[11];
    const float* bn_b  = (const float*)d_in[12];
    const float* bn_m  = (const float*)d_in[13];
    const float* bn_v  = (const float*)d_in[14];
    float* out = (float*)d_out;

    mask_kernel<<<ROWS*32/256, 256>>>(adj);
    gemm1_kernel<<<dim3(FC/64, ROWS/128), 256>>>(feat, Wh);
    s_kernel<<<(ROWS*NH + 255)/256, 256>>>(ah);
    attn1_kernel<<<B_*NH, 256>>>(bn_g, bn_b, bn_m, bn_v);
    lin2_kernel<<<200, 256>>>(Wsent, asent, Wpara, apara, Wqt, aqt);
    attn2_kernel<<<B_, 256>>>(W2, out);
}

// round 3
// speedup vs baseline: 1.0944x; 1.0944x over previous
#include <cuda_runtime.h>
#include <math.h>

#define B_    256
#define N_    200
#define FIN   768
#define HID   32
#define NH    8
#define FC    256                 // NH*HID
#define ROWS  (B_*N_)             // 51200
#define ALPHA 0.3f
#define NEGINF (-9e15f)

// ---------------- scratch (device globals; no allocations allowed) ----------
__device__ float     g_H1[(size_t)ROWS*FC];     // first layer h, [row][head*32+f]
__device__ float     g_X2[(size_t)ROWS*FC];     // post ELU+BN concat features
__device__ float     g_s1[(size_t)NH*ROWS];     // [h][row]
__device__ float     g_s2[(size_t)NH*ROWS];
__device__ unsigned  g_mask[(size_t)ROWS*8];    // 7 words of adj bits per row (pad 8)
__device__ float     g_hs[(size_t)ROWS*2];
__device__ float     g_hp[(size_t)ROWS*2];
__device__ float     g_hq[(size_t)ROWS*HID];
__device__ float     g_s1s[ROWS], g_s2s[ROWS];
__device__ float     g_s1p[ROWS], g_s2p[ROWS];
__device__ float     g_s1q[ROWS], g_s2q[ROWS];

__device__ __forceinline__ float eluf(float v)  { return v > 0.f ? v : expm1f(v); }
__device__ __forceinline__ float lrelu(float v) { return v > 0.f ? v : ALPHA * v; }

// ---- packed f32x2 helpers (Blackwell FFMA2 path) ---------------------------
__device__ __forceinline__ unsigned long long pack2(float lo, float hi) {
    unsigned long long r;
    asm("mov.b64 %0, {%1, %2};" : "=l"(r) : "f"(lo), "f"(hi));
    return r;
}
__device__ __forceinline__ void fma2(unsigned long long& d,
                                     unsigned long long a, unsigned long long b) {
    asm("fma.rn.f32x2 %0, %1, %2, %0;" : "+l"(d) : "l"(a), "l"(b));
}
__device__ __forceinline__ float2 unpack2(unsigned long long v) {
    float2 f;
    asm("mov.b64 {%0, %1}, %2;" : "=f"(f.x), "=f"(f.y) : "l"(v));
    return f;
}

// ---------------- 1) adjacency -> bitmask via ballot -------------------------
__global__ __launch_bounds__(256) void mask_kernel(const int* __restrict__ adj)
{
    int gw   = (blockIdx.x * blockDim.x + threadIdx.x) >> 5;
    int lane = threadIdx.x & 31;
    if (gw >= ROWS) return;
    const int* row = adj + (size_t)gw * N_;
    unsigned*  dst = g_mask + (size_t)gw * 8;
    #pragma unroll
    for (int w = 0; w < 7; ++w) {
        int j = w * 32 + lane;
        int v = (j < N_) ? (row[j] > 0) : 0;
        unsigned bits = __ballot_sync(0xffffffffu, v);
        if (lane == 0) dst[w] = bits;
    }
}

// ---------------- 2) H1 = feat @ Wcat  (M=51200, N=256, K=768) ---------------
// 128x128 tile, 8x8 microtile via packed f32x2 FMA, double-buffered smem.
__global__ __launch_bounds__(256, 2) void gemm1_kernel(const float* __restrict__ A,
                                                       const float* __restrict__ Wh)
{
    // A staged as duplicated 64-bit pairs: As2[k][row] = (a, a)
    __shared__ __align__(16) unsigned long long As2[2][16][128];  // 32 KB
    __shared__ __align__(16) float             Bs [2][16][128];   // 16 KB

    int tid = threadIdx.x;
    int blockRow = blockIdx.y * 128;
    int blockCol = blockIdx.x * 128;
    int tx = tid & 15, ty = tid >> 4;

    // global load mapping
    int aRow = tid >> 2;            // 0..63 (and +64)
    int aK   = (tid & 3) * 4;       // 0,4,8,12
    int bK   = tid >> 5;            // 0..7 (and +8)
    int bC   = (tid & 31) * 4;      // 0..124
    const float* aPtr0 = A + (size_t)(blockRow + aRow)      * FIN + aK;
    const float* aPtr1 = A + (size_t)(blockRow + aRow + 64) * FIN + aK;
    int cb = blockCol + bC;
    const float* bPtr0 = Wh + ((size_t)(cb >> 5) * FIN + bK    ) * HID + (cb & 31);
    const float* bPtr1 = Wh + ((size_t)(cb >> 5) * FIN + bK + 8) * HID + (cb & 31);

    unsigned long long acc[8][4];
    #pragma unroll
    for (int r = 0; r < 8; ++r)
        #pragma unroll
        for (int c = 0; c < 4; ++c) acc[r][c] = 0ull;

    float4 ra0, ra1, rb0, rb1;

    // preload tile 0
    ra0 = *(const float4*)(aPtr0);
    ra1 = *(const float4*)(aPtr1);
    rb0 = *(const float4*)(bPtr0);
    rb1 = *(const float4*)(bPtr1);
    {
        const float* av0 = &ra0.x; const float* av1 = &ra1.x;
        #pragma unroll
        for (int q = 0; q < 4; ++q) {
            As2[0][aK+q][aRow]      = pack2(av0[q], av0[q]);
            As2[0][aK+q][aRow+64]   = pack2(av1[q], av1[q]);
        }
        *(float4*)&Bs[0][bK  ][bC] = rb0;
        *(float4*)&Bs[0][bK+8][bC] = rb1;
    }
    __syncthreads();

    int buf = 0;
    for (int t = 0; t < FIN/16; ++t) {
        int k0n = (t + 1) * 16;
        if (t + 1 < FIN/16) {
            ra0 = *(const float4*)(aPtr0 + k0n);
            ra1 = *(const float4*)(aPtr1 + k0n);
            rb0 = *(const float4*)(bPtr0 + (size_t)k0n * HID);
            rb1 = *(const float4*)(bPtr1 + (size_t)k0n * HID);
        }

        #pragma unroll
        for (int k = 0; k < 16; ++k) {
            ulonglong2 a01 = *(const ulonglong2*)&As2[buf][k][ty*4];
            ulonglong2 a23 = *(const ulonglong2*)&As2[buf][k][ty*4+2];
            ulonglong2 a45 = *(const ulonglong2*)&As2[buf][k][64+ty*4];
            ulonglong2 a67 = *(const ulonglong2*)&As2[buf][k][64+ty*4+2];
            ulonglong2 b01 = *(const ulonglong2*)&Bs[buf][k][tx*4];
            ulonglong2 b23 = *(const ulonglong2*)&Bs[buf][k][64+tx*4];
            fma2(acc[0][0], a01.x, b01.x); fma2(acc[0][1], a01.x, b01.y);
            fma2(acc[0][2], a01.x, b23.x); fma2(acc[0][3], a01.x, b23.y);
            fma2(acc[1][0], a01.y, b01.x); fma2(acc[1][1], a01.y, b01.y);
            fma2(acc[1][2], a01.y, b23.x); fma2(acc[1][3], a01.y, b23.y);
            fma2(acc[2][0], a23.x, b01.x); fma2(acc[2][1], a23.x, b01.y);
            fma2(acc[2][2], a23.x, b23.x); fma2(acc[2][3], a23.x, b23.y);
            fma2(acc[3][0], a23.y, b01.x); fma2(acc[3][1], a23.y, b01.y);
            fma2(acc[3][2], a23.y, b23.x); fma2(acc[3][3], a23.y, b23.y);
            fma2(acc[4][0], a45.x, b01.x); fma2(acc[4][1], a45.x, b01.y);
            fma2(acc[4][2], a45.x, b23.x); fma2(acc[4][3], a45.x, b23.y);
            fma2(acc[5][0], a45.y, b01.x); fma2(acc[5][1], a45.y, b01.y);
            fma2(acc[5][2], a45.y, b23.x); fma2(acc[5][3], a45.y, b23.y);
            fma2(acc[6][0], a67.x, b01.x); fma2(acc[6][1], a67.x, b01.y);
            fma2(acc[6][2], a67.x, b23.x); fma2(acc[6][3], a67.x, b23.y);
            fma2(acc[7][0], a67.y, b01.x); fma2(acc[7][1], a67.y, b01.y);
            fma2(acc[7][2], a67.y, b23.x); fma2(acc[7][3], a67.y, b23.y);
        }

        if (t + 1 < FIN/16) {
            int nb = buf ^ 1;
            const float* av0 = &ra0.x; const float* av1 = &ra1.x;
            #pragma unroll
            for (int q = 0; q < 4; ++q) {
                As2[nb][aK+q][aRow]    = pack2(av0[q], av0[q]);
                As2[nb][aK+q][aRow+64] = pack2(av1[q], av1[q]);
            }
            *(float4*)&Bs[nb][bK  ][bC] = rb0;
            *(float4*)&Bs[nb][bK+8][bC] = rb1;
            __syncthreads();
            buf = nb;
        }
    }

    // epilogue
    #pragma unroll
    for (int r = 0; r < 8; ++r) {
        int row = blockRow + (r < 4 ? ty*4 + r : 64 + ty*4 + (r - 4));
        float2 u0 = unpack2(acc[r][0]);
        float2 u1 = unpack2(acc[r][1]);
        float2 u2 = unpack2(acc[r][2]);
        float2 u3 = unpack2(acc[r][3]);
        *(float4*)(g_H1 + (size_t)row * FC + blockCol + tx*4)      = make_float4(u0.x,u0.y,u1.x,u1.y);
        *(float4*)(g_H1 + (size_t)row * FC + blockCol + 64 + tx*4) = make_float4(u2.x,u2.y,u3.x,u3.y);
    }
}

// ---------------- 3) per-head attention scores s1,s2 -------------------------
__global__ __launch_bounds__(256) void s_kernel(const float* __restrict__ ah)
{
    int gid = blockIdx.x * blockDim.x + threadIdx.x;
    if (gid >= ROWS * NH) return;
    int row = gid >> 3, h = gid & 7;
    const float* a1 = ah + h * 64;
    const float* a2 = a1 + 32;
    const float4* x = (const float4*)(g_H1 + (size_t)row * FC + h * HID);
    float s1 = 0.f, s2 = 0.f;
    #pragma unroll
    for (int t = 0; t < 8; ++t) {
        float4 v = x[t];
        s1 += v.x*a1[4*t] + v.y*a1[4*t+1] + v.z*a1[4*t+2] + v.w*a1[4*t+3];
        s2 += v.x*a2[4*t] + v.y*a2[4*t+1] + v.z*a2[4*t+2] + v.w*a2[4*t+3];
    }
    g_s1[(size_t)h*ROWS + row] = s1;
    g_s2[(size_t)h*ROWS + row] = s2;
}

// ---------------- 4) layer-1 attention + ELU + BN -> X2 ----------------------
// One block per (b,h). m via monotonicity: max_j lrelu(s1+s2j) = lrelu(s1+max s2j).
__global__ __launch_bounds__(224) void attn1_kernel(const float* __restrict__ bn_g,
                                                    const float* __restrict__ bn_b,
                                                    const float* __restrict__ bn_m,
                                                    const float* __restrict__ bn_v)
{
    int b = blockIdx.x >> 3, h = blockIdx.x & 7;
    __shared__ __align__(16) float sh_h[N_*HID];
    __shared__ float sh_s1[N_], sh_s2[N_];
    __shared__ unsigned shm[N_*7];
    int tid = threadIdx.x;
    size_t base = (size_t)b * N_;

    for (int idx = tid; idx < N_*8; idx += 224) {
        int n = idx >> 3, q = idx & 7;
        ((float4*)sh_h)[idx] = *(const float4*)(g_H1 + (base + n) * FC + h*HID + q*4);
    }
    for (int idx = tid; idx < N_; idx += 224) {
        sh_s1[idx] = g_s1[(size_t)h*ROWS + base + idx];
        sh_s2[idx] = g_s2[(size_t)h*ROWS + base + idx];
    }
    for (int idx = tid; idx < N_*7; idx += 224)
        shm[idx] = g_mask[(base + idx/7)*8 + idx%7];
    __syncthreads();

    int i = tid;
    if (i < N_) {
        unsigned mw[7];
        #pragma unroll
        for (int w = 0; w < 7; ++w) mw[w] = shm[i*7 + w];
        float s1i = sh_s1[i];

        // pass 1: masked max of s2
        float maxs2 = -3.4e38f;
        #pragma unroll
        for (int w = 0; w < 6; ++w) {
            unsigned word = mw[w];
            #pragma unroll 8
            for (int jj = 0; jj < 32; ++jj) {
                float v = sh_s2[w*32 + jj];
                if ((word >> jj) & 1) maxs2 = fmaxf(maxs2, v);
            }
        }
        {
            unsigned word = mw[6];
            #pragma unroll
            for (int jj = 0; jj < 8; ++jj) {
                float v = sh_s2[192 + jj];
                if ((word >> jj) & 1) maxs2 = fmaxf(maxs2, v);
            }
        }
        unsigned anyw = mw[0]|mw[1]|mw[2]|mw[3]|mw[4]|mw[5]|mw[6];
        float m = anyw ? lrelu(s1i + maxs2) : NEGINF;

        // pass 2: softmax-weighted sum (packed f32x2 accumulation)
        unsigned long long acc2[16];
        #pragma unroll
        for (int q = 0; q < 16; ++q) acc2[q] = 0ull;
        float l = 0.f;

        #define ATT_STEP(J, WORD, JJ) {                                        \
            float t_ = s1i + sh_s2[J]; t_ = t_ > 0.f ? t_ : ALPHA * t_;        \
            float e_ = ((WORD >> (JJ)) & 1) ? t_ : NEGINF;                     \
            float p_ = __expf(e_ - m);                                         \
            l += p_;                                                           \
            unsigned long long pp_ = pack2(p_, p_);                            \
            const ulonglong2* hv_ = (const ulonglong2*)(sh_h + (J)*HID);       \
            ulonglong2 h0_ = hv_[0], h1_ = hv_[1], h2_ = hv_[2], h3_ = hv_[3]; \
            ulonglong2 h4_ = hv_[4], h5_ = hv_[5], h6_ = hv_[6], h7_ = hv_[7]; \
            fma2(acc2[0],  pp_, h0_.x); fma2(acc2[1],  pp_, h0_.y);            \
            fma2(acc2[2],  pp_, h1_.x); fma2(acc2[3],  pp_, h1_.y);            \
            fma2(acc2[4],  pp_, h2_.x); fma2(acc2[5],  pp_, h2_.y);            \
            fma2(acc2[6],  pp_, h3_.x); fma2(acc2[7],  pp_, h3_.y);            \
            fma2(acc2[8],  pp_, h4_.x); fma2(acc2[9],  pp_, h4_.y);            \
            fma2(acc2[10], pp_, h5_.x); fma2(acc2[11], pp_, h5_.y);            \
            fma2(acc2[12], pp_, h6_.x); fma2(acc2[13], pp_, h6_.y);            \
            fma2(acc2[14], pp_, h7_.x); fma2(acc2[15], pp_, h7_.y); }

        for (int w = 0; w < 6; ++w) {
            unsigned word = mw[w];
            #pragma unroll 4
            for (int jj = 0; jj < 32; ++jj) ATT_STEP(w*32 + jj, word, jj)
        }
        {
            unsigned word = mw[6];
            #pragma unroll
            for (int jj = 0; jj < 8; ++jj) ATT_STEP(192 + jj, word, jj)
        }
        #undef ATT_STEP

        float invl = 1.f / l;
        float inv  = bn_g[i] * rsqrtf(bn_v[i] + 1e-5f);
        float bb   = bn_b[i] - bn_m[i] * inv;
        float* dst = g_X2 + (base + i) * FC + h*HID;
        #pragma unroll
        for (int q = 0; q < 8; ++q) {
            float2 x0 = unpack2(acc2[2*q]);
            float2 x1 = unpack2(acc2[2*q+1]);
            float4 o;
            o.x = eluf(x0.x*invl) * inv + bb;
            o.y = eluf(x0.y*invl) * inv + bb;
            o.z = eluf(x1.x*invl) * inv + bb;
            o.w = eluf(x1.y*invl) * inv + bb;
            *(float4*)(dst + q*4) = o;
        }
    }
}

// ---------------- 5) second-stage linears + attention scalars ----------------
__global__ __launch_bounds__(256) void lin2_kernel(const float* __restrict__ Wsent,
                                                   const float* __restrict__ asent,
                                                   const float* __restrict__ Wpara,
                                                   const float* __restrict__ apara,
                                                   const float* __restrict__ Wqt,
                                                   const float* __restrict__ aqt)
{
    __shared__ float Wall[36*256];
    int tid = threadIdx.x;
    for (int idx = tid; idx < 512; idx += 256) {
        int k = idx >> 1, c = idx & 1;
        Wall[c*256 + k]     = Wsent[idx];
        Wall[(2+c)*256 + k] = Wpara[idx];
    }
    for (int idx = tid; idx < 8192; idx += 256) {
        int k = idx >> 5, f = idx & 31;
        Wall[(4+f)*256 + k] = Wqt[idx];
    }
    __syncthreads();

    int warp = tid >> 5, lane = tid & 31;
    int nwarps = (gridDim.x * 256) >> 5;
    for (int row = blockIdx.x*8 + warp; row < ROWS; row += nwarps) {
        const float* x = g_X2 + (size_t)row * FC;
        float xr[8];
        #pragma unroll
        for (int t = 0; t < 8; ++t) xr[t] = x[lane + 32*t];

        float s1sv=0,s2sv=0,s1pv=0,s2pv=0,s1qv=0,s2qv=0;
        #pragma unroll 4
        for (int c = 0; c < 36; ++c) {
            const float* wc = Wall + c*256;
            float s = 0.f;
            #pragma unroll
            for (int t = 0; t < 8; ++t) s += xr[t] * wc[lane + 32*t];
            #pragma unroll
            for (int o = 16; o; o >>= 1) s += __shfl_xor_sync(0xffffffffu, s, o);
            if (lane == 0) {
                if (c < 2)       { g_hs[row*2+c]   = s; s1sv += s*asent[c];   s2sv += s*asent[2+c]; }
                else if (c < 4)  { int cc=c-2; g_hp[row*2+cc] = s; s1pv += s*apara[cc]; s2pv += s*apara[2+cc]; }
                else             { int f=c-4;  g_hq[(size_t)row*HID+f] = s; s1qv += s*aqt[f]; s2qv += s*aqt[32+f]; }
            }
        }
        if (lane == 0) {
            g_s1s[row]=s1sv; g_s2s[row]=s2sv;
            g_s1p[row]=s1pv; g_s2p[row]=s2pv;
            g_s1q[row]=s1qv; g_s2q[row]=s2qv;
        }
    }
}

// ---------------- 6) final attentions + heads (sent/para full, qt row 0) -----
__global__ __launch_bounds__(256) void attn2_kernel(const float* __restrict__ W2,
                                                    float* __restrict__ out)
{
    int b = blockIdx.x, tid = threadIdx.x;
    __shared__ float s1s[N_], s2s[N_], s1p[N_], s2p[N_];
    __shared__ float hs[N_*2], hp[N_*2];
    __shared__ unsigned shm[N_*7];
    __shared__ float eq[256];
    __shared__ float h0[HID];
    __shared__ float red[2];
    size_t base = (size_t)b * N_;

    for (int idx = tid; idx < N_; idx += 256) {
        s1s[idx]=g_s1s[base+idx]; s2s[idx]=g_s2s[base+idx];
        s1p[idx]=g_s1p[base+idx]; s2p[idx]=g_s2p[base+idx];
    }
    for (int idx = tid; idx < N_*2; idx += 256) {
        hs[idx]=g_hs[base*2+idx]; hp[idx]=g_hp[base*2+idx];
    }
    for (int idx = tid; idx < N_*7; idx += 256)
        shm[idx] = g_mask[(base + idx/7)*8 + idx%7];
    __syncthreads();

    int i = tid;
    if (i < N_) {
        const unsigned* mrow = &shm[i*7];
        float a1 = s1s[i], p1 = s1p[i];
        float ms = -3.4e38f, mp = -3.4e38f;
        for (int j = 0; j < N_; ++j) {
            int bit = (mrow[j>>5] >> (j&31)) & 1;
            float ts = lrelu(a1 + s2s[j]); ts = bit ? ts : NEGINF;
            float tp = lrelu(p1 + s2p[j]); tp = bit ? tp : NEGINF;
            ms = fmaxf(ms, ts); mp = fmaxf(mp, tp);
        }
        float ls=0.f, lp=0.f, as0=0.f, as1=0.f, ap0=0.f, ap1=0.f;
        for (int j = 0; j < N_; ++j) {
            int bit = (mrow[j>>5] >> (j&31)) & 1;
            float ts = lrelu(a1 + s2s[j]); ts = bit ? ts : NEGINF;
            float ps = __expf(ts - ms); ls += ps;
            as0 += ps*hs[j*2]; as1 += ps*hs[j*2+1];
            float tp = lrelu(p1 + s2p[j]); tp = bit ? tp : NEGINF;
            float pp = __expf(tp - mp); lp += pp;
            ap0 += pp*hp[j*2]; ap1 += pp*hp[j*2+1];
        }
        float o0 = as0/ls, o1 = as1/ls;
        out[(base+i)*2+0] = 1.f/(1.f+__expf(-o0));
        out[(base+i)*2+1] = 1.f/(1.f+__expf(-o1));
        float q0 = ap0/lp, q1 = ap1/lp;
        out[102400 + (base+i)*2+0] = eluf(q0);
        out[102400 + (base+i)*2+1] = eluf(q1);
    }

    // qtype: attention row 0 only
    float s1q0 = g_s1q[base];
    if (tid < N_) {
        int bit = (shm[tid>>5] >> (tid&31)) & 1;   // row 0 mask words
        float t = lrelu(s1q0 + g_s2q[base + tid]);
        eq[tid] = bit ? t : NEGINF;
    } else eq[tid] = -3.4e38f;
    __syncthreads();
    if (tid < 32) {
        float v = -3.4e38f;
        for (int j = tid; j < N_; j += 32) v = fmaxf(v, eq[j]);
        #pragma unroll
        for (int o = 16; o; o >>= 1) v = fmaxf(v, __shfl_xor_sync(0xffffffffu, v, o));
        if (tid == 0) red[0] = v;
    }
    __syncthreads();
    float mq = red[0];
    if (tid < N_) eq[tid] = __expf(eq[tid] - mq);
    __syncthreads();
    if (tid < 32) {
        float v = 0.f;
        for (int j = tid; j < N_; j += 32) v += eq[j];
        #pragma unroll
        for (int o = 16; o; o >>= 1) v += __shfl_xor_sync(0xffffffffu, v, o);
        if (tid == 0) red[1] = v;
    }
    __syncthreads();
    float lq = red[1];
    if (tid < 32) {
        float acc = 0.f;
        for (int j = 0; j < N_; ++j) acc += eq[j] * g_hq[(base + j)*HID + tid];
        h0[tid] = acc / lq;
    }
    __syncthreads();
    if (tid < 2) {
        float s = 0.f;
        #pragma unroll
        for (int f = 0; f < HID; ++f) s += h0[f] * W2[f*2 + tid];
        out[204800 + b*2 + tid] = eluf(s);
    }
}

// ---------------------------------------------------------------------------
extern "C" void kernel_launch(void* const* d_in, const int* in_sizes, int n_in,
                              void* d_out, int out_size)
{
    const float* feat  = (const float*)d_in[0];
    const int*   adj   = (const int*)  d_in[1];
    const float* Wh    = (const float*)d_in[2];
    const float* ah    = (const float*)d_in[3];
    const float* Wsent = (const float*)d_in[4];
    const float* asent = (const float*)d_in[5];
    const float* Wpara = (const float*)d_in[6];
    const float* apara = (const float*)d_in[7];
    const float* Wqt   = (const float*)d_in[8];
    const float* aqt   = (const float*)d_in[9];
    const float* W2    = (const float*)d_in[10];
    const float* bn_g  = (const float*)d_in[11];
    const float* bn_b  = (const float*)d_in[12];
    const float* bn_m  = (const float*)d_in[13];
    const float* bn_v  = (const float*)d_in[14];
    float* out = (float*)d_out;

    mask_kernel<<<ROWS*32/256, 256>>>(adj);
    gemm1_kernel<<<dim3(FC/128, ROWS/128), 256>>>(feat, Wh);
    s_kernel<<<(ROWS*NH + 255)/256, 256>>>(ah);
    attn1_kernel<<<B_*NH, 224>>>(bn_g, bn_b, bn_m, bn_v);
    lin2_kernel<<<640, 256>>>(Wsent, asent, Wpara, apara, Wqt, aqt);
    attn2_kernel<<<B_, 256>>>(W2, out);
}

// round 4
// speedup vs baseline: 1.1413x; 1.0429x over previous
#include <cuda_runtime.h>
#include <math.h>

#define B_    256
#define N_    200
#define FIN   768
#define HID   32
#define NH    8
#define FC    256                 // NH*HID
#define ROWS  (B_*N_)             // 51200
#define ALPHA 0.3f
#define NEGINF (-9e15f)

// ---------------- scratch (device globals; no allocations allowed) ----------
__device__ float     g_H1[(size_t)ROWS*FC];     // first layer h, [row][head*32+f]
__device__ float     g_X2[(size_t)ROWS*FC];     // post ELU+BN concat features
__device__ unsigned  g_mask[(size_t)ROWS*8];    // 7 words of adj bits per row (pad 8)
__device__ float     g_hs[(size_t)ROWS*2];
__device__ float     g_hp[(size_t)ROWS*2];
__device__ float     g_hq[(size_t)ROWS*HID];
__device__ float     g_s1s[ROWS], g_s2s[ROWS];
__device__ float     g_s1p[ROWS], g_s2p[ROWS];
__device__ float     g_s1q[ROWS], g_s2q[ROWS];

__device__ __forceinline__ float eluf(float v)  { return v > 0.f ? v : expm1f(v); }
__device__ __forceinline__ float lrelu(float v) { return v > 0.f ? v : ALPHA * v; }

// ---- packed f32x2 helpers (Blackwell FFMA2 path) ---------------------------
__device__ __forceinline__ unsigned long long pack2(float lo, float hi) {
    unsigned long long r;
    asm("mov.b64 %0, {%1, %2};" : "=l"(r) : "f"(lo), "f"(hi));
    return r;
}
__device__ __forceinline__ void fma2(unsigned long long& d,
                                     unsigned long long a, unsigned long long b) {
    asm("fma.rn.f32x2 %0, %1, %2, %0;" : "+l"(d) : "l"(a), "l"(b));
}
__device__ __forceinline__ float2 unpack2(unsigned long long v) {
    float2 f;
    asm("mov.b64 {%0, %1}, %2;" : "=f"(f.x), "=f"(f.y) : "l"(v));
    return f;
}

// ---------------- 1) adjacency -> bitmask via ballot -------------------------
__global__ __launch_bounds__(256) void mask_kernel(const int* __restrict__ adj)
{
    int gw   = (blockIdx.x * blockDim.x + threadIdx.x) >> 5;
    int lane = threadIdx.x & 31;
    if (gw >= ROWS) return;
    const int* row = adj + (size_t)gw * N_;
    unsigned*  dst = g_mask + (size_t)gw * 8;
    #pragma unroll
    for (int w = 0; w < 7; ++w) {
        int j = w * 32 + lane;
        int v = (j < N_) ? (row[j] > 0) : 0;
        unsigned bits = __ballot_sync(0xffffffffu, v);
        if (lane == 0) dst[w] = bits;
    }
}

// ---------------- 2) H1 = feat @ Wcat  (M=51200, N=256, K=768) ---------------
// 128x128 tile, 8x8 microtile via packed f32x2 FMA, double-buffered smem.
__global__ __launch_bounds__(256, 2) void gemm1_kernel(const float* __restrict__ A,
                                                       const float* __restrict__ Wh)
{
    __shared__ __align__(16) unsigned long long As2[2][16][128];  // 32 KB
    __shared__ __align__(16) float             Bs [2][16][128];   // 16 KB

    int tid = threadIdx.x;
    int blockRow = blockIdx.y * 128;
    int blockCol = blockIdx.x * 128;
    int tx = tid & 15, ty = tid >> 4;

    int aRow = tid >> 2;            // 0..63 (and +64)
    int aK   = (tid & 3) * 4;       // 0,4,8,12
    int bK   = tid >> 5;            // 0..7 (and +8)
    int bC   = (tid & 31) * 4;      // 0..124
    const float* aPtr0 = A + (size_t)(blockRow + aRow)      * FIN + aK;
    const float* aPtr1 = A + (size_t)(blockRow + aRow + 64) * FIN + aK;
    int cb = blockCol + bC;
    const float* bPtr0 = Wh + ((size_t)(cb >> 5) * FIN + bK    ) * HID + (cb & 31);
    const float* bPtr1 = Wh + ((size_t)(cb >> 5) * FIN + bK + 8) * HID + (cb & 31);

    unsigned long long acc[8][4];
    #pragma unroll
    for (int r = 0; r < 8; ++r)
        #pragma unroll
        for (int c = 0; c < 4; ++c) acc[r][c] = 0ull;

    float4 ra0, ra1, rb0, rb1;

    ra0 = *(const float4*)(aPtr0);
    ra1 = *(const float4*)(aPtr1);
    rb0 = *(const float4*)(bPtr0);
    rb1 = *(const float4*)(bPtr1);
    {
        const float* av0 = &ra0.x; const float* av1 = &ra1.x;
        #pragma unroll
        for (int q = 0; q < 4; ++q) {
            As2[0][aK+q][aRow]      = pack2(av0[q], av0[q]);
            As2[0][aK+q][aRow+64]   = pack2(av1[q], av1[q]);
        }
        *(float4*)&Bs[0][bK  ][bC] = rb0;
        *(float4*)&Bs[0][bK+8][bC] = rb1;
    }
    __syncthreads();

    int buf = 0;
    for (int t = 0; t < FIN/16; ++t) {
        int k0n = (t + 1) * 16;
        if (t + 1 < FIN/16) {
            ra0 = *(const float4*)(aPtr0 + k0n);
            ra1 = *(const float4*)(aPtr1 + k0n);
            rb0 = *(const float4*)(bPtr0 + (size_t)k0n * HID);
            rb1 = *(const float4*)(bPtr1 + (size_t)k0n * HID);
        }

        #pragma unroll
        for (int k = 0; k < 16; ++k) {
            ulonglong2 a01 = *(const ulonglong2*)&As2[buf][k][ty*4];
            ulonglong2 a23 = *(const ulonglong2*)&As2[buf][k][ty*4+2];
            ulonglong2 a45 = *(const ulonglong2*)&As2[buf][k][64+ty*4];
            ulonglong2 a67 = *(const ulonglong2*)&As2[buf][k][64+ty*4+2];
            ulonglong2 b01 = *(const ulonglong2*)&Bs[buf][k][tx*4];
            ulonglong2 b23 = *(const ulonglong2*)&Bs[buf][k][64+tx*4];
            fma2(acc[0][0], a01.x, b01.x); fma2(acc[0][1], a01.x, b01.y);
            fma2(acc[0][2], a01.x, b23.x); fma2(acc[0][3], a01.x, b23.y);
            fma2(acc[1][0], a01.y, b01.x); fma2(acc[1][1], a01.y, b01.y);
            fma2(acc[1][2], a01.y, b23.x); fma2(acc[1][3], a01.y, b23.y);
            fma2(acc[2][0], a23.x, b01.x); fma2(acc[2][1], a23.x, b01.y);
            fma2(acc[2][2], a23.x, b23.x); fma2(acc[2][3], a23.x, b23.y);
            fma2(acc[3][0], a23.y, b01.x); fma2(acc[3][1], a23.y, b01.y);
            fma2(acc[3][2], a23.y, b23.x); fma2(acc[3][3], a23.y, b23.y);
            fma2(acc[4][0], a45.x, b01.x); fma2(acc[4][1], a45.x, b01.y);
            fma2(acc[4][2], a45.x, b23.x); fma2(acc[4][3], a45.x, b23.y);
            fma2(acc[5][0], a45.y, b01.x); fma2(acc[5][1], a45.y, b01.y);
            fma2(acc[5][2], a45.y, b23.x); fma2(acc[5][3], a45.y, b23.y);
            fma2(acc[6][0], a67.x, b01.x); fma2(acc[6][1], a67.x, b01.y);
            fma2(acc[6][2], a67.x, b23.x); fma2(acc[6][3], a67.x, b23.y);
            fma2(acc[7][0], a67.y, b01.x); fma2(acc[7][1], a67.y, b01.y);
            fma2(acc[7][2], a67.y, b23.x); fma2(acc[7][3], a67.y, b23.y);
        }

        if (t + 1 < FIN/16) {
            int nb = buf ^ 1;
            const float* av0 = &ra0.x; const float* av1 = &ra1.x;
            #pragma unroll
            for (int q = 0; q < 4; ++q) {
                As2[nb][aK+q][aRow]    = pack2(av0[q], av0[q]);
                As2[nb][aK+q][aRow+64] = pack2(av1[q], av1[q]);
            }
            *(float4*)&Bs[nb][bK  ][bC] = rb0;
            *(float4*)&Bs[nb][bK+8][bC] = rb1;
            __syncthreads();
            buf = nb;
        }
    }

    #pragma unroll
    for (int r = 0; r < 8; ++r) {
        int row = blockRow + (r < 4 ? ty*4 + r : 64 + ty*4 + (r - 4));
        float2 u0 = unpack2(acc[r][0]);
        float2 u1 = unpack2(acc[r][1]);
        float2 u2 = unpack2(acc[r][2]);
        float2 u3 = unpack2(acc[r][3]);
        *(float4*)(g_H1 + (size_t)row * FC + blockCol + tx*4)      = make_float4(u0.x,u0.y,u1.x,u1.y);
        *(float4*)(g_H1 + (size_t)row * FC + blockCol + 64 + tx*4) = make_float4(u2.x,u2.y,u3.x,u3.y);
    }
}

// ---------------- 3) layer-1 attention + ELU + BN -> X2 (s1/s2 fused) --------
// One block per (b,h). Thread pair (2i, 2i+1) handles row i, each half = 16 feats.
__global__ __launch_bounds__(448, 2) void attn1_kernel(const float* __restrict__ ah,
                                                       const float* __restrict__ bn_g,
                                                       const float* __restrict__ bn_b,
                                                       const float* __restrict__ bn_m,
                                                       const float* __restrict__ bn_v)
{
    int b = blockIdx.x >> 3, h = blockIdx.x & 7;
    __shared__ __align__(16) float sh_h[N_*HID];      // 25600 B
    __shared__ float sh_s1[N_], sh_s2[N_];
    __shared__ unsigned shm[N_*7];
    __shared__ __align__(16) float sa[64];
    int tid = threadIdx.x;
    size_t base = (size_t)b * N_;

    for (int idx = tid; idx < N_*8; idx += 448) {
        int n = idx >> 3, q = idx & 7;
        ((float4*)sh_h)[idx] = *(const float4*)(g_H1 + (base + n) * FC + h*HID + q*4);
    }
    if (tid < 64) sa[tid] = ah[h*64 + tid];
    for (int idx = tid; idx < N_*7; idx += 448)
        shm[idx] = g_mask[(base + idx/7)*8 + idx%7];
    __syncthreads();

    int i    = tid >> 1;
    int half = tid & 1;
    int i2   = i < N_ ? i : (N_ - 1);     // clamped for safe smem reads
    bool act = (i < N_);

    // ---- fused s1/s2: each half does a 16-feature dot, pair-combine --------
    {
        const float4* hv = (const float4*)(sh_h + i2*HID + half*16);
        float4 v0 = hv[0], v1 = hv[1], v2 = hv[2], v3 = hv[3];
        const float* a1 = sa + half*16;
        const float* a2 = sa + 32 + half*16;
        float s1 = v0.x*a1[0]+v0.y*a1[1]+v0.z*a1[2]+v0.w*a1[3]
                 + v1.x*a1[4]+v1.y*a1[5]+v1.z*a1[6]+v1.w*a1[7]
                 + v2.x*a1[8]+v2.y*a1[9]+v2.z*a1[10]+v2.w*a1[11]
                 + v3.x*a1[12]+v3.y*a1[13]+v3.z*a1[14]+v3.w*a1[15];
        float s2 = v0.x*a2[0]+v0.y*a2[1]+v0.z*a2[2]+v0.w*a2[3]
                 + v1.x*a2[4]+v1.y*a2[5]+v1.z*a2[6]+v1.w*a2[7]
                 + v2.x*a2[8]+v2.y*a2[9]+v2.z*a2[10]+v2.w*a2[11]
                 + v3.x*a2[12]+v3.y*a2[13]+v3.z*a2[14]+v3.w*a2[15];
        s1 += __shfl_xor_sync(0xffffffffu, s1, 1);
        s2 += __shfl_xor_sync(0xffffffffu, s2, 1);
        if (act && half == 0) { sh_s1[i] = s1; sh_s2[i] = s2; }
    }
    __syncthreads();

    // ---- mask words in regs ------------------------------------------------
    unsigned mw[7];
    #pragma unroll
    for (int w = 0; w < 7; ++w) mw[w] = shm[i2*7 + w];

    // ---- pass 1: masked max of s2, split across the pair -------------------
    float mx = -3.4e38f;
    unsigned any = 0;
    {
        int w0 = half ? 4 : 0;
        int w1 = half ? 7 : 4;
        for (int w = w0; w < w1; ++w) {
            unsigned word = mw[w];
            any |= word;
            int jn = (w == 6) ? 8 : 32;
            #pragma unroll 8
            for (int jj = 0; jj < jn; ++jj) {
                float v = sh_s2[w*32 + jj];
                if ((word >> jj) & 1) mx = fmaxf(mx, v);
            }
        }
    }
    mx  = fmaxf(mx, __shfl_xor_sync(0xffffffffu, mx, 1));
    any |= __shfl_xor_sync(0xffffffffu, any, 1);
    float s1i = sh_s1[i2];
    float m = any ? lrelu(s1i + mx) : NEGINF;

    // ---- pass 2: softmax-weighted sum, 16 features per thread (8 fma2) -----
    unsigned long long acc2[8];
    #pragma unroll
    for (int q = 0; q < 8; ++q) acc2[q] = 0ull;
    float l = 0.f;
    const float* hbase = sh_h + half*16;

    #pragma unroll 1
    for (int w = 0; w < 7; ++w) {
        unsigned word = mw[w];
        int jn = (w == 6) ? 8 : 32;
        #pragma unroll 4
        for (int jj = 0; jj < jn; ++jj) {
            int j = w*32 + jj;
            float t = s1i + sh_s2[j];
            t = t > 0.f ? t : ALPHA * t;
            float e = ((word >> jj) & 1) ? t : NEGINF;
            float p = __expf(e - m);
            l += p;
            unsigned long long pp = pack2(p, p);
            const ulonglong2* hv = (const ulonglong2*)(hbase + j*HID);
            ulonglong2 h0 = hv[0], h1 = hv[1], h2 = hv[2], h3 = hv[3];
            fma2(acc2[0], pp, h0.x); fma2(acc2[1], pp, h0.y);
            fma2(acc2[2], pp, h1.x); fma2(acc2[3], pp, h1.y);
            fma2(acc2[4], pp, h2.x); fma2(acc2[5], pp, h2.y);
            fma2(acc2[6], pp, h3.x); fma2(acc2[7], pp, h3.y);
        }
    }

    if (act) {
        float invl = 1.f / l;
        float inv  = bn_g[i] * rsqrtf(bn_v[i] + 1e-5f);
        float bb   = bn_b[i] - bn_m[i] * inv;
        float* dst = g_X2 + (base + i) * FC + h*HID + half*16;
        #pragma unroll
        for (int q = 0; q < 4; ++q) {
            float2 x0 = unpack2(acc2[2*q]);
            float2 x1 = unpack2(acc2[2*q+1]);
            float4 o;
            o.x = eluf(x0.x*invl) * inv + bb;
            o.y = eluf(x0.y*invl) * inv + bb;
            o.z = eluf(x1.x*invl) * inv + bb;
            o.w = eluf(x1.y*invl) * inv + bb;
            *(float4*)(dst + q*4) = o;
        }
    }
}

// ---------------- 4) second-stage linears + attention scalars ----------------
__global__ __launch_bounds__(256) void lin2_kernel(const float* __restrict__ Wsent,
                                                   const float* __restrict__ asent,
                                                   const float* __restrict__ Wpara,
                                                   const float* __restrict__ apara,
                                                   const float* __restrict__ Wqt,
                                                   const float* __restrict__ aqt)
{
    __shared__ float Wall[36*256];
    int tid = threadIdx.x;
    for (int idx = tid; idx < 512; idx += 256) {
        int k = idx >> 1, c = idx & 1;
        Wall[c*256 + k]     = Wsent[idx];
        Wall[(2+c)*256 + k] = Wpara[idx];
    }
    for (int idx = tid; idx < 8192; idx += 256) {
        int k = idx >> 5, f = idx & 31;
        Wall[(4+f)*256 + k] = Wqt[idx];
    }
    __syncthreads();

    int warp = tid >> 5, lane = tid & 31;
    int nwarps = (gridDim.x * 256) >> 5;
    for (int row = blockIdx.x*8 + warp; row < ROWS; row += nwarps) {
        const float* x = g_X2 + (size_t)row * FC;
        float xr[8];
        #pragma unroll
        for (int t = 0; t < 8; ++t) xr[t] = x[lane + 32*t];

        float s1sv=0,s2sv=0,s1pv=0,s2pv=0,s1qv=0,s2qv=0;
        #pragma unroll 4
        for (int c = 0; c < 36; ++c) {
            const float* wc = Wall + c*256;
            float s = 0.f;
            #pragma unroll
            for (int t = 0; t < 8; ++t) s += xr[t] * wc[lane + 32*t];
            #pragma unroll
            for (int o = 16; o; o >>= 1) s += __shfl_xor_sync(0xffffffffu, s, o);
            if (lane == 0) {
                if (c < 2)       { g_hs[row*2+c]   = s; s1sv += s*asent[c];   s2sv += s*asent[2+c]; }
                else if (c < 4)  { int cc=c-2; g_hp[row*2+cc] = s; s1pv += s*apara[cc]; s2pv += s*apara[2+cc]; }
                else             { int f=c-4;  g_hq[(size_t)row*HID+f] = s; s1qv += s*aqt[f]; s2qv += s*aqt[32+f]; }
            }
        }
        if (lane == 0) {
            g_s1s[row]=s1sv; g_s2s[row]=s2sv;
            g_s1p[row]=s1pv; g_s2p[row]=s2pv;
            g_s1q[row]=s1qv; g_s2q[row]=s2qv;
        }
    }
}

// ---------------- 5) final attentions + heads (sent/para full, qt row 0) -----
__global__ __launch_bounds__(256) void attn2_kernel(const float* __restrict__ W2,
                                                    float* __restrict__ out)
{
    int b = blockIdx.x, tid = threadIdx.x;
    __shared__ float s1s[N_], s2s[N_], s1p[N_], s2p[N_];
    __shared__ float hs[N_*2], hp[N_*2];
    __shared__ unsigned shm[N_*7];
    __shared__ float eq[256];
    __shared__ float h0[HID];
    __shared__ float red[2];
    size_t base = (size_t)b * N_;

    for (int idx = tid; idx < N_; idx += 256) {
        s1s[idx]=g_s1s[base+idx]; s2s[idx]=g_s2s[base+idx];
        s1p[idx]=g_s1p[base+idx]; s2p[idx]=g_s2p[base+idx];
    }
    for (int idx = tid; idx < N_*2; idx += 256) {
        hs[idx]=g_hs[base*2+idx]; hp[idx]=g_hp[base*2+idx];
    }
    for (int idx = tid; idx < N_*7; idx += 256)
        shm[idx] = g_mask[(base + idx/7)*8 + idx%7];
    __syncthreads();

    int i = tid;
    if (i < N_) {
        const unsigned* mrow = &shm[i*7];
        float a1 = s1s[i], p1 = s1p[i];
        float ms = -3.4e38f, mp = -3.4e38f;
        for (int j = 0; j < N_; ++j) {
            int bit = (mrow[j>>5] >> (j&31)) & 1;
            float ts = lrelu(a1 + s2s[j]); ts = bit ? ts : NEGINF;
            float tp = lrelu(p1 + s2p[j]); tp = bit ? tp : NEGINF;
            ms = fmaxf(ms, ts); mp = fmaxf(mp, tp);
        }
        float ls=0.f, lp=0.f, as0=0.f, as1=0.f, ap0=0.f, ap1=0.f;
        for (int j = 0; j < N_; ++j) {
            int bit = (mrow[j>>5] >> (j&31)) & 1;
            float ts = lrelu(a1 + s2s[j]); ts = bit ? ts : NEGINF;
            float ps = __expf(ts - ms); ls += ps;
            as0 += ps*hs[j*2]; as1 += ps*hs[j*2+1];
            float tp = lrelu(p1 + s2p[j]); tp = bit ? tp : NEGINF;
            float pp = __expf(tp - mp); lp += pp;
            ap0 += pp*hp[j*2]; ap1 += pp*hp[j*2+1];
        }
        float o0 = as0/ls, o1 = as1/ls;
        out[(base+i)*2+0] = 1.f/(1.f+__expf(-o0));
        out[(base+i)*2+1] = 1.f/(1.f+__expf(-o1));
        float q0 = ap0/lp, q1 = ap1/lp;
        out[102400 + (base+i)*2+0] = eluf(q0);
        out[102400 + (base+i)*2+1] = eluf(q1);
    }

    // qtype: attention row 0 only
    float s1q0 = g_s1q[base];
    if (tid < N_) {
        int bit = (shm[tid>>5] >> (tid&31)) & 1;   // row 0 mask words
        float t = lrelu(s1q0 + g_s2q[base + tid]);
        eq[tid] = bit ? t : NEGINF;
    } else eq[tid] = -3.4e38f;
    __syncthreads();
    if (tid < 32) {
        float v = -3.4e38f;
        for (int j = tid; j < N_; j += 32) v = fmaxf(v, eq[j]);
        #pragma unroll
        for (int o = 16; o; o >>= 1) v = fmaxf(v, __shfl_xor_sync(0xffffffffu, v, o));
        if (tid == 0) red[0] = v;
    }
    __syncthreads();
    float mq = red[0];
    if (tid < N_) eq[tid] = __expf(eq[tid] - mq);
    __syncthreads();
    if (tid < 32) {
        float v = 0.f;
        for (int j = tid; j < N_; j += 32) v += eq[j];
        #pragma unroll
        for (int o = 16; o; o >>= 1) v += __shfl_xor_sync(0xffffffffu, v, o);
        if (tid == 0) red[1] = v;
    }
    __syncthreads();
    float lq = red[1];
    if (tid < 32) {
        float acc = 0.f;
        for (int j = 0; j < N_; ++j) acc += eq[j] * g_hq[(base + j)*HID + tid];
        h0[tid] = acc / lq;
    }
    __syncthreads();
    if (tid < 2) {
        float s = 0.f;
        #pragma unroll
        for (int f = 0; f < HID; ++f) s += h0[f] * W2[f*2 + tid];
        out[204800 + b*2 + tid] = eluf(s);
    }
}

// ---------------------------------------------------------------------------
extern "C" void kernel_launch(void* const* d_in, const int* in_sizes, int n_in,
                              void* d_out, int out_size)
{
    const float* feat  = (const float*)d_in[0];
    const int*   adj   = (const int*)  d_in[1];
    const float* Wh    = (const float*)d_in[2];
    const float* ah    = (const float*)d_in[3];
    const float* Wsent = (const float*)d_in[4];
    const float* asent = (const float*)d_in[5];
    const float* Wpara = (const float*)d_in[6];
    const float* apara = (const float*)d_in[7];
    const float* Wqt   = (const float*)d_in[8];
    const float* aqt   = (const float*)d_in[9];
    const float* W2    = (const float*)d_in[10];
    const float* bn_g  = (const float*)d_in[11];
    const float* bn_b  = (const float*)d_in[12];
    const float* bn_m  = (const float*)d_in[13];
    const float* bn_v  = (const float*)d_in[14];
    float* out = (float*)d_out;

    mask_kernel<<<ROWS*32/256, 256>>>(adj);
    gemm1_kernel<<<dim3(FC/128, ROWS/128), 256>>>(feat, Wh);
    attn1_kernel<<<B_*NH, 448>>>(ah, bn_g, bn_b, bn_m, bn_v);
    lin2_kernel<<<640, 256>>>(Wsent, asent, Wpara, apara, Wqt, aqt);
    attn2_kernel<<<B_, 256>>>(W2, out);
}

// round 5
// speedup vs baseline: 1.3057x; 1.1440x over previous
#include <cuda_runtime.h>
#include <math.h>

#define B_    256
#define N_    200
#define FIN   768
#define HID   32
#define NH    8
#define FC    256                 // NH*HID
#define ROWS  (B_*N_)             // 51200
#define ALPHA 0.3f
#define NEGINF (-9e15f)

// ---------------- scratch (device globals; no allocations allowed) ----------
__device__ float     g_H1[(size_t)ROWS*FC];     // first layer h, [row][head*32+f]
__device__ float     g_X2[(size_t)ROWS*FC];     // post ELU+BN concat features
__device__ unsigned  g_mask[(size_t)ROWS*8];    // 7 words of adj bits per row (pad 8)
__device__ float     g_hs[(size_t)ROWS*2];
__device__ float     g_hp[(size_t)ROWS*2];
__device__ float     g_hq[(size_t)ROWS*HID];
__device__ float     g_s1s[ROWS], g_s2s[ROWS];
__device__ float     g_s1p[ROWS], g_s2p[ROWS];
__device__ float     g_s1q[ROWS], g_s2q[ROWS];

__device__ __forceinline__ float eluf(float v)  { return v > 0.f ? v : expm1f(v); }
__device__ __forceinline__ float lrelu(float v) { return v > 0.f ? v : ALPHA * v; }

// ---- packed f32x2 helpers (Blackwell FFMA2 path) ---------------------------
__device__ __forceinline__ unsigned long long pack2(float lo, float hi) {
    unsigned long long r;
    asm("mov.b64 %0, {%1, %2};" : "=l"(r) : "f"(lo), "f"(hi));
    return r;
}
__device__ __forceinline__ void fma2(unsigned long long& d,
                                     unsigned long long a, unsigned long long b) {
    asm("fma.rn.f32x2 %0, %1, %2, %0;" : "+l"(d) : "l"(a), "l"(b));
}
__device__ __forceinline__ float2 unpack2(unsigned long long v) {
    float2 f;
    asm("mov.b64 {%0, %1}, %2;" : "=f"(f.x), "=f"(f.y) : "l"(v));
    return f;
}

// ---------------- 1) adjacency -> bitmask via ballot -------------------------
__global__ __launch_bounds__(256) void mask_kernel(const int* __restrict__ adj)
{
    int gw   = (blockIdx.x * blockDim.x + threadIdx.x) >> 5;
    int lane = threadIdx.x & 31;
    if (gw >= ROWS) return;
    const int* row = adj + (size_t)gw * N_;
    unsigned*  dst = g_mask + (size_t)gw * 8;
    #pragma unroll
    for (int w = 0; w < 7; ++w) {
        int j = w * 32 + lane;
        int v = (j < N_) ? (row[j] > 0) : 0;
        unsigned bits = __ballot_sync(0xffffffffu, v);
        if (lane == 0) dst[w] = bits;
    }
}

// ---------------- 2) H1 = feat @ Wcat  (M=51200, N=256, K=768) ---------------
// 128x128 tile, 8x8 microtile via packed f32x2 FMA, double-buffered smem.
__global__ __launch_bounds__(256, 2) void gemm1_kernel(const float* __restrict__ A,
                                                       const float* __restrict__ Wh)
{
    __shared__ __align__(16) unsigned long long As2[2][16][128];  // 32 KB
    __shared__ __align__(16) float             Bs [2][16][128];   // 16 KB

    int tid = threadIdx.x;
    int blockRow = blockIdx.y * 128;
    int blockCol = blockIdx.x * 128;
    int tx = tid & 15, ty = tid >> 4;

    int aRow = tid >> 2;            // 0..63 (and +64)
    int aK   = (tid & 3) * 4;       // 0,4,8,12
    int bK   = tid >> 5;            // 0..7 (and +8)
    int bC   = (tid & 31) * 4;      // 0..124
    const float* aPtr0 = A + (size_t)(blockRow + aRow)      * FIN + aK;
    const float* aPtr1 = A + (size_t)(blockRow + aRow + 64) * FIN + aK;
    int cb = blockCol + bC;
    const float* bPtr0 = Wh + ((size_t)(cb >> 5) * FIN + bK    ) * HID + (cb & 31);
    const float* bPtr1 = Wh + ((size_t)(cb >> 5) * FIN + bK + 8) * HID + (cb & 31);

    unsigned long long acc[8][4];
    #pragma unroll
    for (int r = 0; r < 8; ++r)
        #pragma unroll
        for (int c = 0; c < 4; ++c) acc[r][c] = 0ull;

    float4 ra0, ra1, rb0, rb1;

    ra0 = *(const float4*)(aPtr0);
    ra1 = *(const float4*)(aPtr1);
    rb0 = *(const float4*)(bPtr0);
    rb1 = *(const float4*)(bPtr1);
    {
        const float* av0 = &ra0.x; const float* av1 = &ra1.x;
        #pragma unroll
        for (int q = 0; q < 4; ++q) {
            As2[0][aK+q][aRow]      = pack2(av0[q], av0[q]);
            As2[0][aK+q][aRow+64]   = pack2(av1[q], av1[q]);
        }
        *(float4*)&Bs[0][bK  ][bC] = rb0;
        *(float4*)&Bs[0][bK+8][bC] = rb1;
    }
    __syncthreads();

    int buf = 0;
    for (int t = 0; t < FIN/16; ++t) {
        int k0n = (t + 1) * 16;
        if (t + 1 < FIN/16) {
            ra0 = *(const float4*)(aPtr0 + k0n);
            ra1 = *(const float4*)(aPtr1 + k0n);
            rb0 = *(const float4*)(bPtr0 + (size_t)k0n * HID);
            rb1 = *(const float4*)(bPtr1 + (size_t)k0n * HID);
        }

        #pragma unroll
        for (int k = 0; k < 16; ++k) {
            ulonglong2 a01 = *(const ulonglong2*)&As2[buf][k][ty*4];
            ulonglong2 a23 = *(const ulonglong2*)&As2[buf][k][ty*4+2];
            ulonglong2 a45 = *(const ulonglong2*)&As2[buf][k][64+ty*4];
            ulonglong2 a67 = *(const ulonglong2*)&As2[buf][k][64+ty*4+2];
            ulonglong2 b01 = *(const ulonglong2*)&Bs[buf][k][tx*4];
            ulonglong2 b23 = *(const ulonglong2*)&Bs[buf][k][64+tx*4];
            fma2(acc[0][0], a01.x, b01.x); fma2(acc[0][1], a01.x, b01.y);
            fma2(acc[0][2], a01.x, b23.x); fma2(acc[0][3], a01.x, b23.y);
            fma2(acc[1][0], a01.y, b01.x); fma2(acc[1][1], a01.y, b01.y);
            fma2(acc[1][2], a01.y, b23.x); fma2(acc[1][3], a01.y, b23.y);
            fma2(acc[2][0], a23.x, b01.x); fma2(acc[2][1], a23.x, b01.y);
            fma2(acc[2][2], a23.x, b23.x); fma2(acc[2][3], a23.x, b23.y);
            fma2(acc[3][0], a23.y, b01.x); fma2(acc[3][1], a23.y, b01.y);
            fma2(acc[3][2], a23.y, b23.x); fma2(acc[3][3], a23.y, b23.y);
            fma2(acc[4][0], a45.x, b01.x); fma2(acc[4][1], a45.x, b01.y);
            fma2(acc[4][2], a45.x, b23.x); fma2(acc[4][3], a45.x, b23.y);
            fma2(acc[5][0], a45.y, b01.x); fma2(acc[5][1], a45.y, b01.y);
            fma2(acc[5][2], a45.y, b23.x); fma2(acc[5][3], a45.y, b23.y);
            fma2(acc[6][0], a67.x, b01.x); fma2(acc[6][1], a67.x, b01.y);
            fma2(acc[6][2], a67.x, b23.x); fma2(acc[6][3], a67.x, b23.y);
            fma2(acc[7][0], a67.y, b01.x); fma2(acc[7][1], a67.y, b01.y);
            fma2(acc[7][2], a67.y, b23.x); fma2(acc[7][3], a67.y, b23.y);
        }

        if (t + 1 < FIN/16) {
            int nb = buf ^ 1;
            const float* av0 = &ra0.x; const float* av1 = &ra1.x;
            #pragma unroll
            for (int q = 0; q < 4; ++q) {
                As2[nb][aK+q][aRow]    = pack2(av0[q], av0[q]);
                As2[nb][aK+q][aRow+64] = pack2(av1[q], av1[q]);
            }
            *(float4*)&Bs[nb][bK  ][bC] = rb0;
            *(float4*)&Bs[nb][bK+8][bC] = rb1;
            __syncthreads();
            buf = nb;
        }
    }

    #pragma unroll
    for (int r = 0; r < 8; ++r) {
        int row = blockRow + (r < 4 ? ty*4 + r : 64 + ty*4 + (r - 4));
        float2 u0 = unpack2(acc[r][0]);
        float2 u1 = unpack2(acc[r][1]);
        float2 u2 = unpack2(acc[r][2]);
        float2 u3 = unpack2(acc[r][3]);
        *(float4*)(g_H1 + (size_t)row * FC + blockCol + tx*4)      = make_float4(u0.x,u0.y,u1.x,u1.y);
        *(float4*)(g_H1 + (size_t)row * FC + blockCol + 64 + tx*4) = make_float4(u2.x,u2.y,u3.x,u3.y);
    }
}

// ---------------- 3) layer-1 attention + ELU + BN -> X2 (s1/s2 fused) --------
// One block per (b,h). Thread pair (2i, 2i+1) handles row i, each half = 16 feats.
__global__ __launch_bounds__(448, 2) void attn1_kernel(const float* __restrict__ ah,
                                                       const float* __restrict__ bn_g,
                                                       const float* __restrict__ bn_b,
                                                       const float* __restrict__ bn_m,
                                                       const float* __restrict__ bn_v)
{
    int b = blockIdx.x >> 3, h = blockIdx.x & 7;
    __shared__ __align__(16) float sh_h[N_*HID];      // 25600 B
    __shared__ float sh_s1[N_], sh_s2[N_];
    __shared__ unsigned shm[N_*7];
    __shared__ __align__(16) float sa[64];
    int tid = threadIdx.x;
    size_t base = (size_t)b * N_;

    for (int idx = tid; idx < N_*8; idx += 448) {
        int n = idx >> 3, q = idx & 7;
        ((float4*)sh_h)[idx] = *(const float4*)(g_H1 + (base + n) * FC + h*HID + q*4);
    }
    if (tid < 64) sa[tid] = ah[h*64 + tid];
    for (int idx = tid; idx < N_*7; idx += 448)
        shm[idx] = g_mask[(base + idx/7)*8 + idx%7];
    __syncthreads();

    int i    = tid >> 1;
    int half = tid & 1;
    int i2   = i < N_ ? i : (N_ - 1);     // clamped for safe smem reads
    bool act = (i < N_);

    // ---- fused s1/s2: each half does a 16-feature dot, pair-combine --------
    {
        const float4* hv = (const float4*)(sh_h + i2*HID + half*16);
        float4 v0 = hv[0], v1 = hv[1], v2 = hv[2], v3 = hv[3];
        const float* a1 = sa + half*16;
        const float* a2 = sa + 32 + half*16;
        float s1 = v0.x*a1[0]+v0.y*a1[1]+v0.z*a1[2]+v0.w*a1[3]
                 + v1.x*a1[4]+v1.y*a1[5]+v1.z*a1[6]+v1.w*a1[7]
                 + v2.x*a1[8]+v2.y*a1[9]+v2.z*a1[10]+v2.w*a1[11]
                 + v3.x*a1[12]+v3.y*a1[13]+v3.z*a1[14]+v3.w*a1[15];
        float s2 = v0.x*a2[0]+v0.y*a2[1]+v0.z*a2[2]+v0.w*a2[3]
                 + v1.x*a2[4]+v1.y*a2[5]+v1.z*a2[6]+v1.w*a2[7]
                 + v2.x*a2[8]+v2.y*a2[9]+v2.z*a2[10]+v2.w*a2[11]
                 + v3.x*a2[12]+v3.y*a2[13]+v3.z*a2[14]+v3.w*a2[15];
        s1 += __shfl_xor_sync(0xffffffffu, s1, 1);
        s2 += __shfl_xor_sync(0xffffffffu, s2, 1);
        if (act && half == 0) { sh_s1[i] = s1; sh_s2[i] = s2; }
    }
    __syncthreads();

    // ---- mask words in regs ------------------------------------------------
    unsigned mw[7];
    #pragma unroll
    for (int w = 0; w < 7; ++w) mw[w] = shm[i2*7 + w];

    // ---- pass 1: masked max of s2, split across the pair -------------------
    float mx = -3.4e38f;
    unsigned any = 0;
    {
        int w0 = half ? 4 : 0;
        int w1 = half ? 7 : 4;
        for (int w = w0; w < w1; ++w) {
            unsigned word = mw[w];
            any |= word;
            int jn = (w == 6) ? 8 : 32;
            #pragma unroll 8
            for (int jj = 0; jj < jn; ++jj) {
                float v = sh_s2[w*32 + jj];
                if ((word >> jj) & 1) mx = fmaxf(mx, v);
            }
        }
    }
    mx  = fmaxf(mx, __shfl_xor_sync(0xffffffffu, mx, 1));
    any |= __shfl_xor_sync(0xffffffffu, any, 1);
    float s1i = sh_s1[i2];
    float m = any ? lrelu(s1i + mx) : NEGINF;

    // ---- pass 2: softmax-weighted sum, 16 features per thread (8 fma2) -----
    unsigned long long acc2[8];
    #pragma unroll
    for (int q = 0; q < 8; ++q) acc2[q] = 0ull;
    float l = 0.f;
    const float* hbase = sh_h + half*16;

    #pragma unroll 1
    for (int w = 0; w < 7; ++w) {
        unsigned word = mw[w];
        int jn = (w == 6) ? 8 : 32;
        #pragma unroll 4
        for (int jj = 0; jj < jn; ++jj) {
            int j = w*32 + jj;
            float t = s1i + sh_s2[j];
            t = t > 0.f ? t : ALPHA * t;
            float e = ((word >> jj) & 1) ? t : NEGINF;
            float p = __expf(e - m);
            l += p;
            unsigned long long pp = pack2(p, p);
            const ulonglong2* hv = (const ulonglong2*)(hbase + j*HID);
            ulonglong2 h0 = hv[0], h1 = hv[1], h2 = hv[2], h3 = hv[3];
            fma2(acc2[0], pp, h0.x); fma2(acc2[1], pp, h0.y);
            fma2(acc2[2], pp, h1.x); fma2(acc2[3], pp, h1.y);
            fma2(acc2[4], pp, h2.x); fma2(acc2[5], pp, h2.y);
            fma2(acc2[6], pp, h3.x); fma2(acc2[7], pp, h3.y);
        }
    }

    if (act) {
        float invl = 1.f / l;
        float inv  = bn_g[i] * rsqrtf(bn_v[i] + 1e-5f);
        float bb   = bn_b[i] - bn_m[i] * inv;
        float* dst = g_X2 + (base + i) * FC + h*HID + half*16;
        #pragma unroll
        for (int q = 0; q < 4; ++q) {
            float2 x0 = unpack2(acc2[2*q]);
            float2 x1 = unpack2(acc2[2*q+1]);
            float4 o;
            o.x = eluf(x0.x*invl) * inv + bb;
            o.y = eluf(x0.y*invl) * inv + bb;
            o.z = eluf(x1.x*invl) * inv + bb;
            o.w = eluf(x1.y*invl) * inv + bb;
            *(float4*)(dst + q*4) = o;
        }
    }
}

// ---------------- 4) second-stage linears: row-per-thread FFMA2 GEMV ---------
// 36 output cols as 18 packed pairs: pair0=sent(0,1), pair1=para(0,1),
// pairs 2..17 = qt feature pairs. W staged in smem as Wp[k][pair].
__global__ __launch_bounds__(256) void lin2_kernel(const float* __restrict__ Wsent,
                                                   const float* __restrict__ asent,
                                                   const float* __restrict__ Wpara,
                                                   const float* __restrict__ apara,
                                                   const float* __restrict__ Wqt,
                                                   const float* __restrict__ aqt)
{
    __shared__ __align__(16) unsigned long long Wp[256][18];  // 36 KB
    int tid = threadIdx.x;
    for (int idx = tid; idx < 256*18; idx += 256) {
        int k = idx / 18, p = idx - k*18;
        float lo, hi;
        if (p == 0)      { lo = Wsent[k*2];     hi = Wsent[k*2+1]; }
        else if (p == 1) { lo = Wpara[k*2];     hi = Wpara[k*2+1]; }
        else             { int f = (p-2)*2; lo = Wqt[k*32+f]; hi = Wqt[k*32+f+1]; }
        Wp[k][p] = pack2(lo, hi);
    }
    __syncthreads();

    int row = blockIdx.x * 256 + tid;   // grid = 200 blocks, exact cover
    const float4* x4 = (const float4*)(g_X2 + (size_t)row * FC);

    unsigned long long acc2[18];
    #pragma unroll
    for (int p = 0; p < 18; ++p) acc2[p] = 0ull;

    #pragma unroll 2
    for (int kc = 0; kc < 64; ++kc) {
        float4 xv = x4[kc];
        float xs[4] = {xv.x, xv.y, xv.z, xv.w};
        #pragma unroll
        for (int q = 0; q < 4; ++q) {
            int k = kc*4 + q;
            unsigned long long xx = pack2(xs[q], xs[q]);
            const ulonglong2* wr = (const ulonglong2*)&Wp[k][0];
            ulonglong2 w0 = wr[0], w1 = wr[1], w2 = wr[2];
            ulonglong2 w3 = wr[3], w4 = wr[4], w5 = wr[5];
            ulonglong2 w6 = wr[6], w7 = wr[7], w8 = wr[8];
            fma2(acc2[0],  xx, w0.x); fma2(acc2[1],  xx, w0.y);
            fma2(acc2[2],  xx, w1.x); fma2(acc2[3],  xx, w1.y);
            fma2(acc2[4],  xx, w2.x); fma2(acc2[5],  xx, w2.y);
            fma2(acc2[6],  xx, w3.x); fma2(acc2[7],  xx, w3.y);
            fma2(acc2[8],  xx, w4.x); fma2(acc2[9],  xx, w4.y);
            fma2(acc2[10], xx, w5.x); fma2(acc2[11], xx, w5.y);
            fma2(acc2[12], xx, w6.x); fma2(acc2[13], xx, w6.y);
            fma2(acc2[14], xx, w7.x); fma2(acc2[15], xx, w7.y);
            fma2(acc2[16], xx, w8.x); fma2(acc2[17], xx, w8.y);
        }
    }

    float c[36];
    #pragma unroll
    for (int p = 0; p < 18; ++p) {
        float2 u = unpack2(acc2[p]);
        c[2*p] = u.x; c[2*p+1] = u.y;
    }

    *(float2*)(g_hs + (size_t)row*2) = make_float2(c[0], c[1]);
    g_s1s[row] = c[0]*asent[0] + c[1]*asent[1];
    g_s2s[row] = c[0]*asent[2] + c[1]*asent[3];
    *(float2*)(g_hp + (size_t)row*2) = make_float2(c[2], c[3]);
    g_s1p[row] = c[2]*apara[0] + c[3]*apara[1];
    g_s2p[row] = c[2]*apara[2] + c[3]*apara[3];

    float s1q = 0.f, s2q = 0.f;
    #pragma unroll
    for (int f = 0; f < 32; ++f) {
        float v = c[4+f];
        s1q += v * aqt[f];
        s2q += v * aqt[32+f];
    }
    float* hq = g_hq + (size_t)row * HID;
    #pragma unroll
    for (int q = 0; q < 8; ++q)
        *(float4*)(hq + 4*q) = make_float4(c[4+4*q], c[5+4*q], c[6+4*q], c[7+4*q]);
    g_s1q[row] = s1q;
    g_s2q[row] = s2q;
}

// ---------------- 5) final attentions: y==0 -> sent+qtype, y==1 -> para ------
__global__ __launch_bounds__(256) void attn2_kernel(const float* __restrict__ W2,
                                                    float* __restrict__ out)
{
    int b = blockIdx.x, which = blockIdx.y, tid = threadIdx.x;
    __shared__ float s1a[N_], s2a[N_];
    __shared__ float ha[N_*2];
    __shared__ unsigned shm[N_*7];
    __shared__ float eq[256];
    __shared__ float h0[HID];
    __shared__ float red[2];
    size_t base = (size_t)b * N_;

    const float* gs1 = which ? g_s1p : g_s1s;
    const float* gs2 = which ? g_s2p : g_s2s;
    const float* gh  = which ? g_hp  : g_hs;

    for (int idx = tid; idx < N_; idx += 256) {
        s1a[idx] = gs1[base+idx]; s2a[idx] = gs2[base+idx];
    }
    for (int idx = tid; idx < N_*2; idx += 256)
        ha[idx] = gh[base*2+idx];
    for (int idx = tid; idx < N_*7; idx += 256)
        shm[idx] = g_mask[(base + idx/7)*8 + idx%7];
    __syncthreads();

    int i = tid;
    if (i < N_) {
        const unsigned* mrow = &shm[i*7];
        float a1 = s1a[i];
        float ms = -3.4e38f;
        for (int j = 0; j < N_; ++j) {
            int bit = (mrow[j>>5] >> (j&31)) & 1;
            float ts = lrelu(a1 + s2a[j]); ts = bit ? ts : NEGINF;
            ms = fmaxf(ms, ts);
        }
        float ls = 0.f, a0 = 0.f, o1v = 0.f;
        for (int j = 0; j < N_; ++j) {
            int bit = (mrow[j>>5] >> (j&31)) & 1;
            float ts = lrelu(a1 + s2a[j]); ts = bit ? ts : NEGINF;
            float ps = __expf(ts - ms); ls += ps;
            a0 += ps*ha[j*2]; o1v += ps*ha[j*2+1];
        }
        float o0 = a0/ls, o1 = o1v/ls;
        if (which == 0) {
            out[(base+i)*2+0] = 1.f/(1.f+__expf(-o0));
            out[(base+i)*2+1] = 1.f/(1.f+__expf(-o1));
        } else {
            out[102400 + (base+i)*2+0] = eluf(o0);
            out[102400 + (base+i)*2+1] = eluf(o1);
        }
    }

    if (which != 0) return;

    // qtype: attention row 0 only
    float s1q0 = g_s1q[base];
    if (tid < N_) {
        int bit = (shm[tid>>5] >> (tid&31)) & 1;   // row 0 mask words
        float t = lrelu(s1q0 + g_s2q[base + tid]);
        eq[tid] = bit ? t : NEGINF;
    } else eq[tid] = -3.4e38f;
    __syncthreads();
    if (tid < 32) {
        float v = -3.4e38f;
        for (int j = tid; j < N_; j += 32) v = fmaxf(v, eq[j]);
        #pragma unroll
        for (int o = 16; o; o >>= 1) v = fmaxf(v, __shfl_xor_sync(0xffffffffu, v, o));
        if (tid == 0) red[0] = v;
    }
    __syncthreads();
    float mq = red[0];
    if (tid < N_) eq[tid] = __expf(eq[tid] - mq);
    __syncthreads();
    if (tid < 32) {
        float v = 0.f;
        for (int j = tid; j < N_; j += 32) v += eq[j];
        #pragma unroll
        for (int o = 16; o; o >>= 1) v += __shfl_xor_sync(0xffffffffu, v, o);
        if (tid == 0) red[1] = v;
    }
    __syncthreads();
    float lq = red[1];
    if (tid < 32) {
        float acc = 0.f;
        for (int j = 0; j < N_; ++j) acc += eq[j] * g_hq[(base + j)*HID + tid];
        h0[tid] = acc / lq;
    }
    __syncthreads();
    if (tid < 2) {
        float s = 0.f;
        #pragma unroll
        for (int f = 0; f < HID; ++f) s += h0[f] * W2[f*2 + tid];
        out[204800 + b*2 + tid] = eluf(s);
    }
}

// ---------------------------------------------------------------------------
extern "C" void kernel_launch(void* const* d_in, const int* in_sizes, int n_in,
                              void* d_out, int out_size)
{
    const float* feat  = (const float*)d_in[0];
    const int*   adj   = (const int*)  d_in[1];
    const float* Wh    = (const float*)d_in[2];
    const float* ah    = (const float*)d_in[3];
    const float* Wsent = (const float*)d_in[4];
    const float* asent = (const float*)d_in[5];
    const float* Wpara = (const float*)d_in[6];
    const float* apara = (const float*)d_in[7];
    const float* Wqt   = (const float*)d_in[8];
    const float* aqt   = (const float*)d_in[9];
    const float* W2    = (const float*)d_in[10];
    const float* bn_g  = (const float*)d_in[11];
    const float* bn_b  = (const float*)d_in[12];
    const float* bn_m  = (const float*)d_in[13];
    const float* bn_v  = (const float*)d_in[14];
    float* out = (float*)d_out;

    mask_kernel<<<ROWS*32/256, 256>>>(adj);
    gemm1_kernel<<<dim3(FC/128, ROWS/128), 256>>>(feat, Wh);
    attn1_kernel<<<B_*NH, 448>>>(ah, bn_g, bn_b, bn_m, bn_v);
    lin2_kernel<<<ROWS/256, 256>>>(Wsent, asent, Wpara, apara, Wqt, aqt);
    attn2_kernel<<<dim3(B_, 2), 256>>>(W2, out);
}

// round 11
// speedup vs baseline: 1.6065x; 1.2303x over previous
#include <cuda_runtime.h>
#include <cuda_bf16.h>
#include <mma.h>
#include <math.h>
#include <cstdint>

#define B_    256
#define N_    200
#define FIN   768
#define HID   32
#define NH    8
#define FC    256                 // NH*HID
#define ROWS  (B_*N_)             // 51200
#define ALPHA 0.3f
#define NEGINF (-9e15f)

// ---------------- scratch (device globals; no allocations allowed) ----------
__device__ float          g_H1[(size_t)ROWS*FC];
__device__ float          g_X2[(size_t)ROWS*FC];
__device__ unsigned       g_mask[(size_t)ROWS*8];
__device__ __nv_bfloat16  g_Wthi[(size_t)FC*FIN];   // W^T hi, [n][k]
__device__ __nv_bfloat16  g_Wtlo[(size_t)FC*FIN];   // W^T lo
__device__ float          g_hs[(size_t)ROWS*2];
__device__ float          g_hp[(size_t)ROWS*2];
__device__ float          g_hq[(size_t)ROWS*HID];
__device__ float          g_s1s[ROWS], g_s2s[ROWS];
__device__ float          g_s1p[ROWS], g_s2p[ROWS];
__device__ float          g_s1q[ROWS], g_s2q[ROWS];

__device__ __forceinline__ float eluf(float v)  { return v > 0.f ? v : expm1f(v); }
__device__ __forceinline__ float lrelu(float v) { return v > 0.f ? v : ALPHA * v; }

// ---- packed f32x2 helpers ---------------------------------------------------
__device__ __forceinline__ unsigned long long pack2(float lo, float hi) {
    unsigned long long r;
    asm("mov.b64 %0, {%1, %2};" : "=l"(r) : "f"(lo), "f"(hi));
    return r;
}
__device__ __forceinline__ void fma2(unsigned long long& d,
                                     unsigned long long a, unsigned long long b) {
    asm("fma.rn.f32x2 %0, %1, %2, %0;" : "+l"(d) : "l"(a), "l"(b));
}
__device__ __forceinline__ float2 unpack2(unsigned long long v) {
    float2 f;
    asm("mov.b64 {%0, %1}, %2;" : "=f"(f.x), "=f"(f.y) : "l"(v));
    return f;
}

// ---------------- 1) adjacency -> bitmask ------------------------------------
__global__ __launch_bounds__(256) void mask_kernel(const int* __restrict__ adj)
{
    int gw   = (blockIdx.x * blockDim.x + threadIdx.x) >> 5;
    int lane = threadIdx.x & 31;
    if (gw >= ROWS) return;
    const int* row = adj + (size_t)gw * N_;
    unsigned*  dst = g_mask + (size_t)gw * 8;
    #pragma unroll
    for (int w = 0; w < 7; ++w) {
        int j = w * 32 + lane;
        int v = (j < N_) ? (row[j] > 0) : 0;
        unsigned bits = __ballot_sync(0xffffffffu, v);
        if (lane == 0) dst[w] = bits;
    }
}

// ---------------- 1b) W -> W^T bf16 hi/lo ------------------------------------
__global__ __launch_bounds__(256) void wcvt_kernel(const float* __restrict__ Wh)
{
    int k = blockIdx.x;       // 0..767
    int n = threadIdx.x;      // 0..255
    float w = Wh[(size_t)(n >> 5) * FIN * HID + (size_t)k * HID + (n & 31)];
    __nv_bfloat16 h = __float2bfloat16(w);
    g_Wthi[(size_t)n * FIN + k] = h;
    g_Wtlo[(size_t)n * FIN + k] = __float2bfloat16(w - __bfloat162float(h));
}

// ---------------- 2) H1 = feat @ Wcat via wmma bf16-split --------------------
// CTA 128x128, 8 warps of 32x64 (2x4 wmma 16x16 c-frags), K chunks of 32.
// NOTE: FIN/32 = 24 chunks (R8-R10 bug: ran only 12 -> half of K).
#define ASTR 40   // bf16 elems per smem row (multiple of 8 for wmma ldm)
__global__ __launch_bounds__(256) void gemm1_mma_kernel(const float* __restrict__ feat)
{
    using namespace nvcuda;
    __shared__ __align__(16) __nv_bfloat16 sAhi[128*ASTR];
    __shared__ __align__(16) __nv_bfloat16 sAlo[128*ASTR];
    __shared__ __align__(16) __nv_bfloat16 sBhi[128*ASTR];
    __shared__ __align__(16) __nv_bfloat16 sBlo[128*ASTR];

    int tid = threadIdx.x, wid = tid >> 5;
    int blockRow = blockIdx.y * 128, colBase = blockIdx.x * 128;

    int lrow = tid >> 1, lhalf = tid & 1;
    const float* aPtr = feat + (size_t)(blockRow + lrow) * FIN + lhalf * 16;
    const __nv_bfloat16* bhPtr = g_Wthi + (size_t)(colBase + lrow) * FIN + lhalf * 16;
    const __nv_bfloat16* blPtr = g_Wtlo + (size_t)(colBase + lrow) * FIN + lhalf * 16;
    uint32_t sOffA = (uint32_t)(lrow * ASTR + lhalf * 16) * 2;  // bytes

    int m0 = (wid & 3) * 32, n0 = (wid >> 2) * 64;

    wmma::fragment<wmma::accumulator, 16, 16, 16, float> cf[2][4];
    #pragma unroll
    for (int mt = 0; mt < 2; ++mt)
        #pragma unroll
        for (int nt = 0; nt < 4; ++nt)
            wmma::fill_fragment(cf[mt][nt], 0.f);

    for (int c = 0; c < FIN/32; ++c) {     // 24 chunks == full K
        int k0 = c * 32;
        // ---- stage A: fp32 -> bf16 hi/lo ----
        {
            const float* ap = aPtr + k0;
            float4 f0 = *(const float4*)(ap);
            float4 f1 = *(const float4*)(ap + 4);
            float4 f2 = *(const float4*)(ap + 8);
            float4 f3 = *(const float4*)(ap + 12);
            uint32_t h[8], l[8];
            float fs[16] = {f0.x,f0.y,f0.z,f0.w, f1.x,f1.y,f1.z,f1.w,
                            f2.x,f2.y,f2.z,f2.w, f3.x,f3.y,f3.z,f3.w};
            #pragma unroll
            for (int q = 0; q < 8; ++q) {
                __nv_bfloat162 hh = __floats2bfloat162_rn(fs[2*q], fs[2*q+1]);
                __nv_bfloat162 ll = __floats2bfloat162_rn(
                    fs[2*q]   - __bfloat162float(hh.x),
                    fs[2*q+1] - __bfloat162float(hh.y));
                h[q] = *(uint32_t*)&hh;
                l[q] = *(uint32_t*)&ll;
            }
            uint4* dH = (uint4*)((char*)sAhi + sOffA);
            uint4* dL = (uint4*)((char*)sAlo + sOffA);
            dH[0] = make_uint4(h[0],h[1],h[2],h[3]);
            dH[1] = make_uint4(h[4],h[5],h[6],h[7]);
            dL[0] = make_uint4(l[0],l[1],l[2],l[3]);
            dL[1] = make_uint4(l[4],l[5],l[6],l[7]);
        }
        // ---- stage B: preconverted bf16 ----
        {
            const uint4* bh = (const uint4*)(bhPtr + k0);
            const uint4* bl = (const uint4*)(blPtr + k0);
            uint4* dH = (uint4*)((char*)sBhi + sOffA);
            uint4* dL = (uint4*)((char*)sBlo + sOffA);
            dH[0] = bh[0]; dH[1] = bh[1];
            dL[0] = bl[0]; dL[1] = bl[1];
        }
        __syncthreads();

        #pragma unroll
        for (int ks = 0; ks < 32; ks += 16) {
            wmma::fragment<wmma::matrix_a, 16, 16, 16, __nv_bfloat16, wmma::row_major> aH[2], aL[2];
            #pragma unroll
            for (int mt = 0; mt < 2; ++mt) {
                wmma::load_matrix_sync(aH[mt], &sAhi[(m0 + mt*16) * ASTR + ks], ASTR);
                wmma::load_matrix_sync(aL[mt], &sAlo[(m0 + mt*16) * ASTR + ks], ASTR);
            }
            #pragma unroll
            for (int nt = 0; nt < 4; ++nt) {
                wmma::fragment<wmma::matrix_b, 16, 16, 16, __nv_bfloat16, wmma::col_major> bH, bL;
                wmma::load_matrix_sync(bH, &sBhi[(n0 + nt*16) * ASTR + ks], ASTR);
                wmma::load_matrix_sync(bL, &sBlo[(n0 + nt*16) * ASTR + ks], ASTR);
                #pragma unroll
                for (int mt = 0; mt < 2; ++mt) {
                    wmma::mma_sync(cf[mt][nt], aH[mt], bH, cf[mt][nt]);
                    wmma::mma_sync(cf[mt][nt], aH[mt], bL, cf[mt][nt]);
                    wmma::mma_sync(cf[mt][nt], aL[mt], bH, cf[mt][nt]);
                }
            }
        }
        __syncthreads();
    }

    // epilogue: compiler-managed fragment stores
    #pragma unroll
    for (int mt = 0; mt < 2; ++mt)
        #pragma unroll
        for (int nt = 0; nt < 4; ++nt) {
            int gm = blockRow + m0 + mt*16;
            int gn = colBase + n0 + nt*16;
            wmma::store_matrix_sync(&g_H1[(size_t)gm * FC + gn], cf[mt][nt],
                                    FC, wmma::mem_row_major);
        }
}

// ---------------- 3) layer-1 attention + ELU + BN -> X2 (s1/s2 fused) --------
__global__ __launch_bounds__(448, 2) void attn1_kernel(const float* __restrict__ ah,
                                                       const float* __restrict__ bn_g,
                                                       const float* __restrict__ bn_b,
                                                       const float* __restrict__ bn_m,
                                                       const float* __restrict__ bn_v)
{
    int b = blockIdx.x >> 3, h = blockIdx.x & 7;
    __shared__ __align__(16) float sh_h[N_*HID];
    __shared__ float sh_s1[N_], sh_s2[N_];
    __shared__ unsigned shm[N_*7];
    __shared__ __align__(16) float sa[64];
    int tid = threadIdx.x;
    size_t base = (size_t)b * N_;

    for (int idx = tid; idx < N_*8; idx += 448) {
        int n = idx >> 3, q = idx & 7;
        ((float4*)sh_h)[idx] = *(const float4*)(g_H1 + (base + n) * FC + h*HID + q*4);
    }
    if (tid < 64) sa[tid] = ah[h*64 + tid];
    for (int idx = tid; idx < N_*7; idx += 448)
        shm[idx] = g_mask[(base + idx/7)*8 + idx%7];
    __syncthreads();

    int i    = tid >> 1;
    int half = tid & 1;
    int i2   = i < N_ ? i : (N_ - 1);
    bool act = (i < N_);

    {
        const float4* hv = (const float4*)(sh_h + i2*HID + half*16);
        float4 v0 = hv[0], v1 = hv[1], v2 = hv[2], v3 = hv[3];
        const float* a1 = sa + half*16;
        const float* a2 = sa + 32 + half*16;
        float s1 = v0.x*a1[0]+v0.y*a1[1]+v0.z*a1[2]+v0.w*a1[3]
                 + v1.x*a1[4]+v1.y*a1[5]+v1.z*a1[6]+v1.w*a1[7]
                 + v2.x*a1[8]+v2.y*a1[9]+v2.z*a1[10]+v2.w*a1[11]
                 + v3.x*a1[12]+v3.y*a1[13]+v3.z*a1[14]+v3.w*a1[15];
        float s2 = v0.x*a2[0]+v0.y*a2[1]+v0.z*a2[2]+v0.w*a2[3]
                 + v1.x*a2[4]+v1.y*a2[5]+v1.z*a2[6]+v1.w*a2[7]
                 + v2.x*a2[8]+v2.y*a2[9]+v2.z*a2[10]+v2.w*a2[11]
                 + v3.x*a2[12]+v3.y*a2[13]+v3.z*a2[14]+v3.w*a2[15];
        s1 += __shfl_xor_sync(0xffffffffu, s1, 1);
        s2 += __shfl_xor_sync(0xffffffffu, s2, 1);
        if (act && half == 0) { sh_s1[i] = s1; sh_s2[i] = s2; }
    }
    __syncthreads();

    unsigned mw[7];
    #pragma unroll
    for (int w = 0; w < 7; ++w) mw[w] = shm[i2*7 + w];

    float mx = -3.4e38f;
    unsigned any = 0;
    {
        int w0 = half ? 4 : 0;
        int w1 = half ? 7 : 4;
        for (int w = w0; w < w1; ++w) {
            unsigned word = mw[w];
            any |= word;
            int jn = (w == 6) ? 8 : 32;
            #pragma unroll 8
            for (int jj = 0; jj < jn; ++jj) {
                float v = sh_s2[w*32 + jj];
                if ((word >> jj) & 1) mx = fmaxf(mx, v);
            }
        }
    }
    mx  = fmaxf(mx, __shfl_xor_sync(0xffffffffu, mx, 1));
    any |= __shfl_xor_sync(0xffffffffu, any, 1);
    float s1i = sh_s1[i2];
    float m = any ? lrelu(s1i + mx) : NEGINF;

    unsigned long long acc2[8];
    #pragma unroll
    for (int q = 0; q < 8; ++q) acc2[q] = 0ull;
    float l = 0.f;
    const float* hbase = sh_h + half*16;

    #pragma unroll 1
    for (int w = 0; w < 7; ++w) {
        unsigned word = mw[w];
        int jn = (w == 6) ? 8 : 32;
        #pragma unroll 4
        for (int jj = 0; jj < jn; ++jj) {
            int j = w*32 + jj;
            float t = s1i + sh_s2[j];
            t = t > 0.f ? t : ALPHA * t;
            float e = ((word >> jj) & 1) ? t : NEGINF;
            float p = __expf(e - m);
            l += p;
            unsigned long long pp = pack2(p, p);
            const ulonglong2* hv = (const ulonglong2*)(hbase + j*HID);
            ulonglong2 h0 = hv[0], h1 = hv[1], h2 = hv[2], h3 = hv[3];
            fma2(acc2[0], pp, h0.x); fma2(acc2[1], pp, h0.y);
            fma2(acc2[2], pp, h1.x); fma2(acc2[3], pp, h1.y);
            fma2(acc2[4], pp, h2.x); fma2(acc2[5], pp, h2.y);
            fma2(acc2[6], pp, h3.x); fma2(acc2[7], pp, h3.y);
        }
    }

    if (act) {
        float invl = 1.f / l;
        float inv  = bn_g[i] * rsqrtf(bn_v[i] + 1e-5f);
        float bb   = bn_b[i] - bn_m[i] * inv;
        float* dst = g_X2 + (base + i) * FC + h*HID + half*16;
        #pragma unroll
        for (int q = 0; q < 4; ++q) {
            float2 x0 = unpack2(acc2[2*q]);
            float2 x1 = unpack2(acc2[2*q+1]);
            float4 o;
            o.x = eluf(x0.x*invl) * inv + bb;
            o.y = eluf(x0.y*invl) * inv + bb;
            o.z = eluf(x1.x*invl) * inv + bb;
            o.w = eluf(x1.y*invl) * inv + bb;
            *(float4*)(dst + q*4) = o;
        }
    }
}

// ---------------- 4) second-stage linears: row-per-thread FFMA2 GEMV ---------
__global__ __launch_bounds__(256) void lin2_kernel(const float* __restrict__ Wsent,
                                                   const float* __restrict__ asent,
                                                   const float* __restrict__ Wpara,
                                                   const float* __restrict__ apara,
                                                   const float* __restrict__ Wqt,
                                                   const float* __restrict__ aqt)
{
    __shared__ __align__(16) unsigned long long Wp[256][18];
    int tid = threadIdx.x;
    for (int idx = tid; idx < 256*18; idx += 256) {
        int k = idx / 18, p = idx - k*18;
        float lo, hi;
        if (p == 0)      { lo = Wsent[k*2];     hi = Wsent[k*2+1]; }
        else if (p == 1) { lo = Wpara[k*2];     hi = Wpara[k*2+1]; }
        else             { int f = (p-2)*2; lo = Wqt[k*32+f]; hi = Wqt[k*32+f+1]; }
        Wp[k][p] = pack2(lo, hi);
    }
    __syncthreads();

    int row = blockIdx.x * 256 + tid;
    const float4* x4 = (const float4*)(g_X2 + (size_t)row * FC);

    unsigned long long acc2[18];
    #pragma unroll
    for (int p = 0; p < 18; ++p) acc2[p] = 0ull;

    #pragma unroll 2
    for (int kc = 0; kc < 64; ++kc) {
        float4 xv = x4[kc];
        float xs[4] = {xv.x, xv.y, xv.z, xv.w};
        #pragma unroll
        for (int q = 0; q < 4; ++q) {
            int k = kc*4 + q;
            unsigned long long xx = pack2(xs[q], xs[q]);
            const ulonglong2* wr = (const ulonglong2*)&Wp[k][0];
            ulonglong2 w0 = wr[0], w1 = wr[1], w2 = wr[2];
            ulonglong2 w3 = wr[3], w4 = wr[4], w5 = wr[5];
            ulonglong2 w6 = wr[6], w7 = wr[7], w8 = wr[8];
            fma2(acc2[0],  xx, w0.x); fma2(acc2[1],  xx, w0.y);
            fma2(acc2[2],  xx, w1.x); fma2(acc2[3],  xx, w1.y);
            fma2(acc2[4],  xx, w2.x); fma2(acc2[5],  xx, w2.y);
            fma2(acc2[6],  xx, w3.x); fma2(acc2[7],  xx, w3.y);
            fma2(acc2[8],  xx, w4.x); fma2(acc2[9],  xx, w4.y);
            fma2(acc2[10], xx, w5.x); fma2(acc2[11], xx, w5.y);
            fma2(acc2[12], xx, w6.x); fma2(acc2[13], xx, w6.y);
            fma2(acc2[14], xx, w7.x); fma2(acc2[15], xx, w7.y);
            fma2(acc2[16], xx, w8.x); fma2(acc2[17], xx, w8.y);
        }
    }

    float c[36];
    #pragma unroll
    for (int p = 0; p < 18; ++p) {
        float2 u = unpack2(acc2[p]);
        c[2*p] = u.x; c[2*p+1] = u.y;
    }

    *(float2*)(g_hs + (size_t)row*2) = make_float2(c[0], c[1]);
    g_s1s[row] = c[0]*asent[0] + c[1]*asent[1];
    g_s2s[row] = c[0]*asent[2] + c[1]*asent[3];
    *(float2*)(g_hp + (size_t)row*2) = make_float2(c[2], c[3]);
    g_s1p[row] = c[2]*apara[0] + c[3]*apara[1];
    g_s2p[row] = c[2]*apara[2] + c[3]*apara[3];

    float s1q = 0.f, s2q = 0.f;
    #pragma unroll
    for (int f = 0; f < 32; ++f) {
        float v = c[4+f];
        s1q += v * aqt[f];
        s2q += v * aqt[32+f];
    }
    float* hq = g_hq + (size_t)row * HID;
    #pragma unroll
    for (int q = 0; q < 8; ++q)
        *(float4*)(hq + 4*q) = make_float4(c[4+4*q], c[5+4*q], c[6+4*q], c[7+4*q]);
    g_s1q[row] = s1q;
    g_s2q[row] = s2q;
}

// ---------------- 5) final attentions: y==0 -> sent+qtype, y==1 -> para ------
__global__ __launch_bounds__(256) void attn2_kernel(const float* __restrict__ W2,
                                                    float* __restrict__ out)
{
    int b = blockIdx.x, which = blockIdx.y, tid = threadIdx.x;
    __shared__ float s1a[N_], s2a[N_];
    __shared__ float ha[N_*2];
    __shared__ unsigned shm[N_*7];
    __shared__ float eq[256];
    __shared__ float h0[HID];
    __shared__ float red[2];
    size_t base = (size_t)b * N_;

    const float* gs1 = which ? g_s1p : g_s1s;
    const float* gs2 = which ? g_s2p : g_s2s;
    const float* gh  = which ? g_hp  : g_hs;

    for (int idx = tid; idx < N_; idx += 256) {
        s1a[idx] = gs1[base+idx]; s2a[idx] = gs2[base+idx];
    }
    for (int idx = tid; idx < N_*2; idx += 256)
        ha[idx] = gh[base*2+idx];
    for (int idx = tid; idx < N_*7; idx += 256)
        shm[idx] = g_mask[(base + idx/7)*8 + idx%7];
    __syncthreads();

    int i = tid;
    if (i < N_) {
        const unsigned* mrow = &shm[i*7];
        float a1 = s1a[i];
        float ms = -3.4e38f;
        for (int j = 0; j < N_; ++j) {
            int bit = (mrow[j>>5] >> (j&31)) & 1;
            float ts = lrelu(a1 + s2a[j]); ts = bit ? ts : NEGINF;
            ms = fmaxf(ms, ts);
        }
        float ls = 0.f, a0 = 0.f, o1v = 0.f;
        for (int j = 0; j < N_; ++j) {
            int bit = (mrow[j>>5] >> (j&31)) & 1;
            float ts = lrelu(a1 + s2a[j]); ts = bit ? ts : NEGINF;
            float ps = __expf(ts - ms); ls += ps;
            a0 += ps*ha[j*2]; o1v += ps*ha[j*2+1];
        }
        float o0 = a0/ls, o1 = o1v/ls;
        if (which == 0) {
            out[(base+i)*2+0] = 1.f/(1.f+__expf(-o0));
            out[(base+i)*2+1] = 1.f/(1.f+__expf(-o1));
        } else {
            out[102400 + (base+i)*2+0] = eluf(o0);
            out[102400 + (base+i)*2+1] = eluf(o1);
        }
    }

    if (which != 0) return;

    float s1q0 = g_s1q[base];
    if (tid < N_) {
        int bit = (shm[tid>>5] >> (tid&31)) & 1;
        float t = lrelu(s1q0 + g_s2q[base + tid]);
        eq[tid] = bit ? t : NEGINF;
    } else eq[tid] = -3.4e38f;
    __syncthreads();
    if (tid < 32) {
        float v = -3.4e38f;
        for (int j = tid; j < N_; j += 32) v = fmaxf(v, eq[j]);
        #pragma unroll
        for (int o = 16; o; o >>= 1) v = fmaxf(v, __shfl_xor_sync(0xffffffffu, v, o));
        if (tid == 0) red[0] = v;
    }
    __syncthreads();
    float mq = red[0];
    if (tid < N_) eq[tid] = __expf(eq[tid] - mq);
    __syncthreads();
    if (tid < 32) {
        float v = 0.f;
        for (int j = tid; j < N_; j += 32) v += eq[j];
        #pragma unroll
        for (int o = 16; o; o >>= 1) v += __shfl_xor_sync(0xffffffffu, v, o);
        if (tid == 0) red[1] = v;
    }
    __syncthreads();
    float lq = red[1];
    if (tid < 32) {
        float acc = 0.f;
        for (int j = 0; j < N_; ++j) acc += eq[j] * g_hq[(base + j)*HID + tid];
        h0[tid] = acc / lq;
    }
    __syncthreads();
    if (tid < 2) {
        float s = 0.f;
        #pragma unroll
        for (int f = 0; f < HID; ++f) s += h0[f] * W2[f*2 + tid];
        out[204800 + b*2 + tid] = eluf(s);
    }
}

// ---------------------------------------------------------------------------
extern "C" void kernel_launch(void* const* d_in, const int* in_sizes, int n_in,
                              void* d_out, int out_size)
{
    const float* feat  = (const float*)d_in[0];
    const int*   adj   = (const int*)  d_in[1];
    const float* Wh    = (const float*)d_in[2];
    const float* ah    = (const float*)d_in[3];
    const float* Wsent = (const float*)d_in[4];
    const float* asent = (const float*)d_in[5];
    const float* Wpara = (const float*)d_in[6];
    const float* apara = (const float*)d_in[7];
    const float* Wqt   = (const float*)d_in[8];
    const float* aqt   = (const float*)d_in[9];
    const float* W2    = (const float*)d_in[10];
    const float* bn_g  = (const float*)d_in[11];
    const float* bn_b  = (const float*)d_in[12];
    const float* bn_m  = (const float*)d_in[13];
    const float* bn_v  = (const float*)d_in[14];
    float* out = (float*)d_out;

    mask_kernel<<<ROWS*32/256, 256>>>(adj);
    wcvt_kernel<<<FIN, 256>>>(Wh);
    gemm1_mma_kernel<<<dim3(2, 400), 256>>>(feat);
    attn1_kernel<<<B_*NH, 448>>>(ah, bn_g, bn_b, bn_m, bn_v);
    lin2_kernel<<<ROWS/256, 256>>>(Wsent, asent, Wpara, apara, Wqt, aqt);
    attn2_kernel<<<dim3(B_, 2), 256>>>(W2, out);
}